// round 1
// baseline (speedup 1.0000x reference)
#include <cuda_runtime.h>
#include <math.h>
#include <float.h>

#define B_ 8
#define T_ 48
#define N_ 512
#define F_ 16
#define S_ 12
#define H_ 128
#define NH_ 8
#define HZ_ 6
#define NC_ 3
#define BN_ (B_*N_)   /* 4096 */

#define OFF_REG   0L
#define OFF_RISK  24576L
#define OFF_WARN  98304L
#define OFF_TATTN 122880L
#define OFF_ALPHA 9560064L

// ---------------- scratch (device globals; no allocation) ----------------
__device__ float g_W2T[16*384];       // fused (proj->in_w) weight, transposed [f][row]
__device__ float g_b2[384];           // fused bias
__device__ float g_hlast[BN_*H_];     // h (pre-LN) at t=T-1
__device__ float g_olast[BN_*H_];     // attention output (head-merged) at t=T-1
__device__ float g_tmp[BN_*H_];       // attnproj / ffn2 output
__device__ float g_hln1[BN_*H_];
__device__ float g_ffn1[BN_*2*H_];
__device__ float g_trepr[BN_*H_];
__device__ float g_srepr[N_*H_];
__device__ float g_node3[BN_*3*H_];   // [t_repr | s_repr | g_repr]
__device__ float g_gh[BN_*H_];
__device__ float g_fused[BN_*H_];
__device__ float g_s1[BN_];
__device__ float g_s2[BN_];

// ---------------- helpers ----------------
__device__ __forceinline__ float warp_red_sum(float v) {
    #pragma unroll
    for (int o = 16; o > 0; o >>= 1) v += __shfl_xor_sync(0xffffffffu, v, o);
    return v;
}
__device__ __forceinline__ float warp_red_max(float v) {
    #pragma unroll
    for (int o = 16; o > 0; o >>= 1) v = fmaxf(v, __shfl_xor_sync(0xffffffffu, v, o));
    return v;
}

// ---------------- W2 = in_w @ proj_w ; b2 = in_w @ proj_b + in_b ----------------
__global__ void prepw2_kernel(const float* __restrict__ in_w, const float* __restrict__ in_b,
                              const float* __restrict__ proj_w, const float* __restrict__ proj_b)
{
    int j = blockIdx.x;            // 0..383
    int lane = threadIdx.x;        // 32
    float wreg[4];
    #pragma unroll
    for (int u = 0; u < 4; u++) wreg[u] = in_w[j*H_ + lane + 32*u];
    float pb = 0.f;
    #pragma unroll
    for (int u = 0; u < 4; u++) pb += wreg[u] * proj_b[lane + 32*u];
    pb = warp_red_sum(pb);
    if (lane == 0) g_b2[j] = pb + in_b[j];
    for (int f = 0; f < 16; f++) {
        float s = 0.f;
        #pragma unroll
        for (int u = 0; u < 4; u++) s += wreg[u] * proj_w[(lane + 32*u)*16 + f];
        s = warp_red_sum(s);
        if (lane == 0) g_W2T[f*384 + j] = s;
    }
}

// ---------------- h at t=T-1 (for residual) ----------------
__global__ __launch_bounds__(128) void hlast_kernel(const float* __restrict__ x,
    const float* __restrict__ proj_w, const float* __restrict__ proj_b)
{
    int bn = blockIdx.x; int b = bn >> 9, n = bn & 511;
    int tid = threadIdx.x;
    __shared__ float sx[16];
    if (tid < 16) sx[tid] = x[(((long)b*T_ + (T_-1))*N_ + n)*F_ + tid];
    __syncthreads();
    float s = proj_b[tid];
    #pragma unroll
    for (int f = 0; f < 16; f++) s = fmaf(sx[f], proj_w[tid*16 + f], s);
    g_hlast[(long)bn*H_ + tid] = s;
}

// ---------------- fused attention: qkv-from-x, scores, softmax, t_attn, o(last) ----------------
// dynamic shared layout (floats):
//  sW   [0,6144)        W2T
//  sb2  [6144,6528)
//  sx   [6528,7344)     48 x 17
//  sqkv [7344,16608)    48 x 193  (group of 4 heads: q16|k16|v16 per head)
//  ssc  [16608,18960)   48 x 49
//  tacc [18960,21312)   48 x 49
//  alast[21312,21360)
#define ATTN_SMEM_FLOATS 21360

__global__ __launch_bounds__(256) void attn_kernel(const float* __restrict__ x,
                                                   float* __restrict__ tattn)
{
    extern __shared__ float sm[];
    float* sW    = sm;
    float* sb2   = sm + 6144;
    float* sx    = sm + 6528;
    float* sqkv  = sm + 7344;
    float* ssc   = sm + 16608;
    float* tacc  = sm + 18960;
    float* alast = sm + 21312;

    const int bn = blockIdx.x;
    const int b = bn >> 9, n = bn & 511;
    const int tid = threadIdx.x;
    const int lane = tid & 31, wid = tid >> 5;

    for (int idx = tid; idx < 16*384; idx += 256) sW[idx] = g_W2T[idx];
    for (int idx = tid; idx < 384; idx += 256)    sb2[idx] = g_b2[idx];
    for (int idx = tid; idx < T_*F_; idx += 256) {
        int t = idx >> 4, f = idx & 15;
        sx[t*17 + f] = x[(((long)b*T_ + t)*N_ + n)*F_ + f];
    }
    for (int idx = tid; idx < T_*T_; idx += 256)
        tacc[(idx/T_)*49 + (idx%T_)] = 0.f;
    __syncthreads();

    for (int g = 0; g < 2; g++) {
        // --- qkv for heads 4g..4g+3 into sqkv[t][hh*48 + part*16 + f] ---
        {
            int wrow[6];
            #pragma unroll
            for (int j = 0; j < 6; j++) {
                int c = lane + 32*j;
                int hh = c / 48, rr = c % 48;
                wrow[j] = (rr >> 4)*128 + (4*g + hh)*16 + (rr & 15);
            }
            float acc[6][6];
            #pragma unroll
            for (int i = 0; i < 6; i++)
                #pragma unroll
                for (int j = 0; j < 6; j++) acc[i][j] = sb2[wrow[j]];
            #pragma unroll
            for (int f = 0; f < 16; f++) {
                float av[6], bv[6];
                #pragma unroll
                for (int i = 0; i < 6; i++) av[i] = sx[(wid*6 + i)*17 + f];
                #pragma unroll
                for (int j = 0; j < 6; j++) bv[j] = sW[f*384 + wrow[j]];
                #pragma unroll
                for (int i = 0; i < 6; i++)
                    #pragma unroll
                    for (int j = 0; j < 6; j++)
                        acc[i][j] = fmaf(av[i], bv[j], acc[i][j]);
            }
            #pragma unroll
            for (int i = 0; i < 6; i++)
                #pragma unroll
                for (int j = 0; j < 6; j++)
                    sqkv[(wid*6 + i)*193 + lane + 32*j] = acc[i][j];
        }
        __syncthreads();

        for (int hh = 0; hh < 4; hh++) {
            const int base = hh*48;
            // --- scores 48x48 (3x3 thread tiles) ---
            {
                int ti = tid >> 4, tj = tid & 15;
                int i0 = ti*3, j0 = tj*3;
                float acc[3][3] = {};
                #pragma unroll
                for (int f = 0; f < 16; f++) {
                    float qv[3], kv[3];
                    #pragma unroll
                    for (int r = 0; r < 3; r++) qv[r] = sqkv[(i0+r)*193 + base + f];
                    #pragma unroll
                    for (int c = 0; c < 3; c++) kv[c] = sqkv[(j0+c)*193 + base + 16 + f];
                    #pragma unroll
                    for (int r = 0; r < 3; r++)
                        #pragma unroll
                        for (int c = 0; c < 3; c++)
                            acc[r][c] = fmaf(qv[r], kv[c], acc[r][c]);
                }
                #pragma unroll
                for (int r = 0; r < 3; r++)
                    #pragma unroll
                    for (int c = 0; c < 3; c++)
                        ssc[(i0+r)*49 + j0 + c] = acc[r][c]*0.25f;
            }
            __syncthreads();
            // --- softmax (warp owns rows 6*wid..6*wid+5), accumulate t_attn ---
            #pragma unroll
            for (int rr = 0; rr < 6; rr++) {
                int i = wid*6 + rr;
                float v0 = ssc[i*49 + lane];
                float v1 = (lane < 16) ? ssc[i*49 + 32 + lane] : -FLT_MAX;
                float m = warp_red_max(fmaxf(v0, v1));
                float e0 = __expf(v0 - m);
                float e1 = (lane < 16) ? __expf(v1 - m) : 0.f;
                float ssum = warp_red_sum(e0 + e1);
                float inv = 1.f/ssum;
                float a0 = e0*inv, a1 = e1*inv;
                tacc[i*49 + lane] += a0*0.125f;
                if (lane < 16) tacc[i*49 + 32 + lane] += a1*0.125f;
                if (i == T_-1) {
                    alast[lane] = a0;
                    if (lane < 16) alast[32 + lane] = a1;
                }
            }
            __syncthreads();
            // --- o at last query position for this head ---
            if (tid < 16) {
                float s = 0.f;
                #pragma unroll
                for (int k = 0; k < T_; k++)
                    s = fmaf(alast[k], sqkv[k*193 + base + 32 + tid], s);
                g_olast[(long)bn*H_ + (4*g + hh)*16 + tid] = s;
            }
            __syncthreads();
        }
    }
    for (int idx = tid; idx < T_*T_; idx += 256)
        tattn[(long)bn*(T_*T_) + idx] = tacc[(idx/T_)*49 + (idx%T_)];
}

// ---------------- generic tiled GEMM: C = A @ op(B) + bias, epilogue ----------------
// bt=1: B is (N,K) row-major (use B^T). bt=0: B is (K,N) row-major.
// Block: 32 rows x 128 cols. epi: 0 none, 1 relu, 2 gelu(exact).
__global__ __launch_bounds__(256) void gemm_kernel(
    const float* __restrict__ A, const float* __restrict__ Bm,
    const float* __restrict__ bias, float* __restrict__ C,
    int K, int lda, int ldb, int ldc, int bt, int epi,
    long strA, long strB, long strC)
{
    A  += (long)blockIdx.z * strA;
    Bm += (long)blockIdx.z * strB;
    C  += (long)blockIdx.z * strC;
    const int rowbase = blockIdx.x * 32;
    const int colbase = blockIdx.y * 128;
    __shared__ float As[32][33];
    __shared__ float Bs[32][132];
    const int tid = threadIdx.x;
    const int tx = tid & 31, ty = tid >> 5;
    float acc[4][4] = {};
    for (int k0 = 0; k0 < K; k0 += 32) {
        #pragma unroll
        for (int it = 0; it < 4; it++) {
            int idx = tid + it*256;
            int r = idx >> 5, kk = idx & 31;
            As[kk][r] = A[(long)(rowbase + r)*lda + k0 + kk];
        }
        if (bt) {
            #pragma unroll
            for (int it = 0; it < 16; it++) {
                int idx = tid + it*256;
                int c = idx >> 5, kk = idx & 31;
                Bs[kk][c] = Bm[(long)(colbase + c)*ldb + k0 + kk];
            }
        } else {
            #pragma unroll
            for (int it = 0; it < 16; it++) {
                int idx = tid + it*256;
                int kk = idx >> 7, c = idx & 127;
                Bs[kk][c] = Bm[(long)(k0 + kk)*ldb + colbase + c];
            }
        }
        __syncthreads();
        #pragma unroll
        for (int kk = 0; kk < 32; kk++) {
            float a[4], bb[4];
            #pragma unroll
            for (int i = 0; i < 4; i++) a[i] = As[kk][ty + 8*i];
            #pragma unroll
            for (int j = 0; j < 4; j++) bb[j] = Bs[kk][tx + 32*j];
            #pragma unroll
            for (int i = 0; i < 4; i++)
                #pragma unroll
                for (int j = 0; j < 4; j++)
                    acc[i][j] = fmaf(a[i], bb[j], acc[i][j]);
        }
        __syncthreads();
    }
    #pragma unroll
    for (int i = 0; i < 4; i++) {
        int r = rowbase + ty + 8*i;
        #pragma unroll
        for (int j = 0; j < 4; j++) {
            int c = colbase + tx + 32*j;
            float v = acc[i][j];
            if (bias) v += bias[c];
            if (epi == 1) v = fmaxf(v, 0.f);
            else if (epi == 2) v = 0.5f*v*(1.f + erff(v*0.70710678118654752f));
            C[(long)r*ldc + c] = v;
        }
    }
}

// ---------------- LayerNorm(a + res) * g + b ----------------
__global__ __launch_bounds__(128) void ln_kernel(
    const float* __restrict__ a, const float* __restrict__ res,
    const float* __restrict__ gw, const float* __restrict__ bw,
    float* __restrict__ out)
{
    int row = blockIdx.x, tid = threadIdx.x;
    __shared__ float red[4];
    long base = (long)row*H_;
    float v = a[base + tid] + res[base + tid];
    float s = warp_red_sum(v);
    if ((tid & 31) == 0) red[tid >> 5] = s;
    __syncthreads();
    float mean = (red[0]+red[1]+red[2]+red[3]) * (1.f/H_);
    __syncthreads();
    float d = v - mean;
    float s2 = warp_red_sum(d*d);
    if ((tid & 31) == 0) red[tid >> 5] = s2;
    __syncthreads();
    float var = (red[0]+red[1]+red[2]+red[3]) * (1.f/H_);
    out[base + tid] = d * rsqrtf(var + 1e-5f) * gw[tid] + bw[tid];
}

// ---------------- static features: relu(x_static @ stat_w^T + stat_b) ----------------
__global__ __launch_bounds__(128) void srepr_kernel(const float* __restrict__ xs,
    const float* __restrict__ stat_w, const float* __restrict__ stat_b)
{
    int n = blockIdx.x, tid = threadIdx.x;
    __shared__ float sxs[S_];
    if (tid < S_) sxs[tid] = xs[n*S_ + tid];
    __syncthreads();
    float s = stat_b[tid];
    #pragma unroll
    for (int f = 0; f < S_; f++) s = fmaf(sxs[f], stat_w[tid*S_ + f], s);
    g_srepr[(long)n*H_ + tid] = fmaxf(s, 0.f);
}

// ---------------- node3[:,0:256] = [t_repr | s_repr] ----------------
__global__ void nodebuild_kernel()
{
    long idx = (long)blockIdx.x*256 + threadIdx.x;   // < 4096*256
    int bn = (int)(idx >> 8); int c = (int)(idx & 255);
    float v = (c < H_) ? g_trepr[(long)bn*H_ + c]
                       : g_srepr[(long)(bn & 511)*H_ + (c - H_)];
    g_node3[(long)bn*384 + c] = v;
}

// ---------------- s1 = gh.a1, s2 = gh.a2 ----------------
__global__ void s1s2_kernel(const float* __restrict__ gat_a)
{
    int row = blockIdx.x*8 + (threadIdx.x >> 5);
    int lane = threadIdx.x & 31;
    float p1 = 0.f, p2 = 0.f;
    #pragma unroll
    for (int u = 0; u < 4; u++) {
        int c = lane + 32*u;
        float gv = g_gh[(long)row*H_ + c];
        p1 = fmaf(gv, gat_a[c], p1);
        p2 = fmaf(gv, gat_a[H_ + c], p2);
    }
    p1 = warp_red_sum(p1); p2 = warp_red_sum(p2);
    if (lane == 0) { g_s1[row] = p1; g_s2[row] = p2; }
}

// ---------------- GAT attention alpha (masked softmax over 512 neighbors) ----------------
__global__ __launch_bounds__(256) void alpha_kernel(const int* __restrict__ adj,
                                                    float* __restrict__ out_alpha)
{
    int bi = blockIdx.x;
    int b = bi >> 9, i = bi & 511;
    int tid = threadIdx.x;
    __shared__ float red[8];
    float s1v = g_s1[b*N_ + i];
    float e[2];
    float mloc = -FLT_MAX;
    #pragma unroll
    for (int u = 0; u < 2; u++) {
        int j = tid + u*256;
        float v = s1v + g_s2[b*N_ + j];
        v = (v >= 0.f) ? v : 0.2f*v;
        if (adj[i*N_ + j] == 0) v = -FLT_MAX;
        e[u] = v;
        mloc = fmaxf(mloc, v);
    }
    mloc = warp_red_max(mloc);
    if ((tid & 31) == 0) red[tid >> 5] = mloc;
    __syncthreads();
    float m = red[0];
    #pragma unroll
    for (int w = 1; w < 8; w++) m = fmaxf(m, red[w]);
    __syncthreads();
    float sloc = 0.f;
    #pragma unroll
    for (int u = 0; u < 2; u++) {
        e[u] = (e[u] == -FLT_MAX) ? 0.f : __expf(e[u] - m);
        sloc += e[u];
    }
    sloc = warp_red_sum(sloc);
    if ((tid & 31) == 0) red[tid >> 5] = sloc;
    __syncthreads();
    float s = red[0]+red[1]+red[2]+red[3]+red[4]+red[5]+red[6]+red[7];
    float inv = 1.f/s;
    #pragma unroll
    for (int u = 0; u < 2; u++)
        out_alpha[((long)(b*N_ + i))*N_ + tid + u*256] = e[u]*inv;
}

// ---------------- output heads ----------------
__global__ __launch_bounds__(128) void heads_kernel(
    const float* __restrict__ reg_w,  const float* __restrict__ reg_b,
    const float* __restrict__ risk_w, const float* __restrict__ risk_b,
    const float* __restrict__ warn_w, const float* __restrict__ warn_b,
    float* __restrict__ out)
{
    int bn = blockIdx.x;
    __shared__ float row[H_];
    int tid = threadIdx.x;
    row[tid] = g_fused[(long)bn*H_ + tid];
    __syncthreads();
    if (tid < 30) {
        const float* w; float bb; long off;
        if (tid < 6)       { w = reg_w  + tid*H_;        bb = reg_b[tid];       off = OFF_REG  + (long)bn*6  + tid; }
        else if (tid < 24) { int k = tid-6;  w = risk_w + k*H_; bb = risk_b[k]; off = OFF_RISK + (long)bn*18 + k; }
        else               { int k = tid-24; w = warn_w + k*H_; bb = warn_b[k]; off = OFF_WARN + (long)bn*6  + k; }
        float s = bb;
        #pragma unroll 8
        for (int c = 0; c < H_; c++) s = fmaf(row[c], w[c], s);
        out[off] = s;
    }
}

// ---------------- launch ----------------
extern "C" void kernel_launch(void* const* d_in, const int* in_sizes, int n_in,
                              void* d_out, int out_size)
{
    const float* x        = (const float*)d_in[0];
    const float* x_static = (const float*)d_in[1];
    const int*   adj      = (const int*)  d_in[2];
    const float* proj_w   = (const float*)d_in[3];
    const float* proj_b   = (const float*)d_in[4];
    const float* in_w     = (const float*)d_in[5];
    const float* in_b     = (const float*)d_in[6];
    const float* out_w    = (const float*)d_in[7];
    const float* out_b    = (const float*)d_in[8];
    const float* ln1_g    = (const float*)d_in[9];
    const float* ln1_b    = (const float*)d_in[10];
    const float* ffn_w1   = (const float*)d_in[11];
    const float* ffn_b1   = (const float*)d_in[12];
    const float* ffn_w2   = (const float*)d_in[13];
    const float* ffn_b2   = (const float*)d_in[14];
    const float* ln2_g    = (const float*)d_in[15];
    const float* ln2_b    = (const float*)d_in[16];
    const float* stat_w   = (const float*)d_in[17];
    const float* stat_b   = (const float*)d_in[18];
    const float* gat_w    = (const float*)d_in[19];
    const float* gat_a    = (const float*)d_in[20];
    const float* fuse_w   = (const float*)d_in[21];
    const float* fuse_b   = (const float*)d_in[22];
    const float* reg_w    = (const float*)d_in[23];
    const float* reg_b    = (const float*)d_in[24];
    const float* risk_w   = (const float*)d_in[25];
    const float* risk_b   = (const float*)d_in[26];
    const float* warn_w   = (const float*)d_in[27];
    const float* warn_b   = (const float*)d_in[28];
    float* out = (float*)d_out;

    float *p_olast, *p_tmp, *p_hlast, *p_hln1, *p_ffn1, *p_trepr, *p_node3, *p_gh, *p_fused;
    cudaGetSymbolAddress((void**)&p_olast, g_olast);
    cudaGetSymbolAddress((void**)&p_tmp,   g_tmp);
    cudaGetSymbolAddress((void**)&p_hlast, g_hlast);
    cudaGetSymbolAddress((void**)&p_hln1,  g_hln1);
    cudaGetSymbolAddress((void**)&p_ffn1,  g_ffn1);
    cudaGetSymbolAddress((void**)&p_trepr, g_trepr);
    cudaGetSymbolAddress((void**)&p_node3, g_node3);
    cudaGetSymbolAddress((void**)&p_gh,    g_gh);
    cudaGetSymbolAddress((void**)&p_fused, g_fused);

    const int ATTN_SMEM = ATTN_SMEM_FLOATS * 4;  // 85440 bytes
    cudaFuncSetAttribute(attn_kernel, cudaFuncAttributeMaxDynamicSharedMemorySize, ATTN_SMEM);

    // transformer (fused-weight path)
    prepw2_kernel<<<384, 32>>>(in_w, in_b, proj_w, proj_b);
    hlast_kernel<<<BN_, 128>>>(x, proj_w, proj_b);
    attn_kernel<<<BN_, 256, ATTN_SMEM>>>(x, out + OFF_TATTN);

    // out-proj (last position) + LN1
    gemm_kernel<<<dim3(BN_/32,1,1),256>>>(p_olast, out_w, out_b, p_tmp,
        128, 128, 128, 128, 1, 0, 0, 0, 0);
    ln_kernel<<<BN_, 128>>>(p_tmp, p_hlast, ln1_g, ln1_b, p_hln1);

    // FFN (last position) + LN2
    gemm_kernel<<<dim3(BN_/32,2,1),256>>>(p_hln1, ffn_w1, ffn_b1, p_ffn1,
        128, 128, 128, 256, 1, 2, 0, 0, 0);
    gemm_kernel<<<dim3(BN_/32,1,1),256>>>(p_ffn1, ffn_w2, ffn_b2, p_tmp,
        256, 256, 256, 128, 1, 0, 0, 0, 0);
    ln_kernel<<<BN_, 128>>>(p_tmp, p_hln1, ln2_g, ln2_b, p_trepr);

    // GAT
    srepr_kernel<<<N_, 128>>>(x_static, stat_w, stat_b);
    nodebuild_kernel<<<BN_, 256>>>();
    gemm_kernel<<<dim3(BN_/32,1,1),256>>>(p_node3, gat_w, (const float*)nullptr, p_gh,
        256, 384, 256, 128, 1, 0, 0, 0, 0);
    s1s2_kernel<<<N_, 256>>>(gat_a);
    alpha_kernel<<<BN_, 256>>>(adj, out + OFF_ALPHA);
    // g_repr = alpha @ gh  (batched over B), written into node3[:,256:384]
    gemm_kernel<<<dim3(N_/32,1,B_),256>>>(out + OFF_ALPHA, p_gh, (const float*)nullptr,
        p_node3 + 256, 512, 512, 128, 384, 0, 0,
        (long)N_*N_, (long)N_*H_, (long)N_*384);
    // fused projection + heads
    gemm_kernel<<<dim3(BN_/32,1,1),256>>>(p_node3, fuse_w, fuse_b, p_fused,
        384, 384, 384, 128, 1, 1, 0, 0, 0);
    heads_kernel<<<BN_, 128>>>(reg_w, reg_b, risk_w, risk_b, warn_w, warn_b, out);

    (void)in_sizes; (void)n_in; (void)out_size;
}

// round 2
// speedup vs baseline: 1.1107x; 1.1107x over previous
#include <cuda_runtime.h>
#include <math.h>
#include <float.h>

#define B_ 8
#define T_ 48
#define N_ 512
#define F_ 16
#define S_ 12
#define H_ 128
#define NH_ 8
#define HZ_ 6
#define NC_ 3
#define BN_ (B_*N_)   /* 4096 */

#define OFF_REG   0L
#define OFF_RISK  24576L
#define OFF_WARN  98304L
#define OFF_TATTN 122880L
#define OFF_ALPHA 9560064L

// ---------------- scratch ----------------
__device__ __align__(16) float g_W2T[16*384];   // fused (in_w@proj_w) weight, [f][row]
__device__ __align__(16) float g_b2[384];
__device__ __align__(16) float g_Mh[8*256];     // per-head Wq^T Wk (scaled 0.25)
__device__ __align__(16) float g_rh[8*16];
__device__ __align__(16) float g_ch[8*16];
__device__ __align__(16) float g_cst[8];
__device__ __align__(16) float g_hlast[BN_*H_];
__device__ __align__(16) float g_olast[BN_*H_];
__device__ __align__(16) float g_hln1[BN_*H_];
__device__ __align__(16) float g_ffn1[BN_*2*H_];
__device__ __align__(16) float g_node3[BN_*3*H_];
__device__ __align__(16) float g_gh[BN_*H_];
__device__ __align__(16) float g_fused[BN_*H_];
__device__ __align__(16) float g_s1[BN_];
__device__ __align__(16) float g_s2[BN_];

// ---------------- helpers ----------------
__device__ __forceinline__ float warp_red_sum(float v) {
    #pragma unroll
    for (int o = 16; o > 0; o >>= 1) v += __shfl_xor_sync(0xffffffffu, v, o);
    return v;
}
__device__ __forceinline__ float warp_red_max(float v) {
    #pragma unroll
    for (int o = 16; o > 0; o >>= 1) v = fmaxf(v, __shfl_xor_sync(0xffffffffu, v, o));
    return v;
}

// ---------------- W2 = in_w @ proj_w ; b2 = in_w @ proj_b + in_b ----------------
__global__ void prepw2_kernel(const float* __restrict__ in_w, const float* __restrict__ in_b,
                              const float* __restrict__ proj_w, const float* __restrict__ proj_b)
{
    int j = blockIdx.x;            // 0..383
    int lane = threadIdx.x;        // 32
    float wreg[4];
    #pragma unroll
    for (int u = 0; u < 4; u++) wreg[u] = in_w[j*H_ + lane + 32*u];
    float pb = 0.f;
    #pragma unroll
    for (int u = 0; u < 4; u++) pb += wreg[u] * proj_b[lane + 32*u];
    pb = warp_red_sum(pb);
    if (lane == 0) g_b2[j] = pb + in_b[j];
    for (int f = 0; f < 16; f++) {
        float s = 0.f;
        #pragma unroll
        for (int u = 0; u < 4; u++) s += wreg[u] * proj_w[(lane + 32*u)*16 + f];
        s = warp_red_sum(s);
        if (lane == 0) g_W2T[f*384 + j] = s;
    }
}

// ---------------- per-head score matrices: M = 0.25*Wq^T Wk ----------------
__global__ __launch_bounds__(256) void prep2m_kernel()
{
    int h = blockIdx.x;
    int f = threadIdx.x >> 4, g = threadIdx.x & 15;
    float s = 0.f;
    #pragma unroll
    for (int d = 0; d < 16; d++)
        s = fmaf(g_W2T[f*384 + h*16 + d], g_W2T[g*384 + 128 + h*16 + d], s);
    g_Mh[h*256 + f*16 + g] = 0.25f*s;
}
__global__ void prep2rc_kernel()
{
    int h = blockIdx.x, tid = threadIdx.x;
    if (tid < 16) {
        float s = 0.f;
        #pragma unroll
        for (int d = 0; d < 16; d++)
            s = fmaf(g_W2T[tid*384 + h*16 + d], g_b2[128 + h*16 + d], s);
        g_rh[h*16 + tid] = 0.25f*s;
    } else if (tid < 32) {
        int g = tid - 16;
        float s = 0.f;
        #pragma unroll
        for (int d = 0; d < 16; d++)
            s = fmaf(g_b2[h*16 + d], g_W2T[g*384 + 128 + h*16 + d], s);
        g_ch[h*16 + g] = 0.25f*s;
    } else if (tid == 32) {
        float s = 0.f;
        #pragma unroll
        for (int d = 0; d < 16; d++)
            s = fmaf(g_b2[h*16 + d], g_b2[128 + h*16 + d], s);
        g_cst[h] = 0.25f*s;
    }
}

// ---------------- h at t=T-1 (residual) ----------------
__global__ __launch_bounds__(128) void hlast_kernel(const float* __restrict__ x,
    const float* __restrict__ proj_w, const float* __restrict__ proj_b)
{
    int bn = blockIdx.x; int b = bn >> 9, n = bn & 511;
    int tid = threadIdx.x;
    __shared__ float sx[16];
    if (tid < 16) sx[tid] = x[(((long)b*T_ + (T_-1))*N_ + n)*F_ + tid];
    __syncthreads();
    float s = proj_b[tid];
    #pragma unroll
    for (int f = 0; f < 16; f++) s = fmaf(sx[f], proj_w[tid*16 + f], s);
    g_hlast[(long)bn*H_ + tid] = s;
}

// ---------------- s_repr -> node3[:,128:256] ----------------
__global__ __launch_bounds__(128) void srepr2_kernel(const float* __restrict__ xs,
    const float* __restrict__ stat_w, const float* __restrict__ stat_b)
{
    int n = blockIdx.x, tid = threadIdx.x;
    __shared__ float sxs[S_];
    if (tid < S_) sxs[tid] = xs[n*S_ + tid];
    __syncthreads();
    float s = stat_b[tid];
    #pragma unroll
    for (int f = 0; f < S_; f++) s = fmaf(sxs[f], stat_w[tid*S_ + f], s);
    s = fmaxf(s, 0.f);
    #pragma unroll
    for (int b = 0; b < B_; b++)
        g_node3[((long)(b*N_ + n))*384 + 128 + tid] = s;
}

// ---------------- attention v2 ----------------
// smem (floats):
#define AX   0        /* sX  48*17 = 816 */
#define AM   816      /* sM  8*256 = 2048 */
#define AR   2864     /* 128 */
#define AC   2992     /* 128 */
#define ACST 3120     /* 8 */
#define AY   3128     /* 4*48*17 = 3264 */
#define AS   6392     /* 4*48*49 = 9408 */
#define AU   15800    /* 192 */
#define AW   15992    /* 192 */
#define AAL  16184    /* 192 */
#define AXB  16376    /* 64 */
#define ATTN2_FLOATS 16440

__global__ __launch_bounds__(256,3) void attn2_kernel(const float* __restrict__ x,
                                                      float* __restrict__ tattn)
{
    extern __shared__ float sm[];
    const int bn = blockIdx.x;
    const int b = bn >> 9, n = bn & 511;
    const int tid = threadIdx.x;

    // load x tile (48x16) -> sX padded 17
    if (tid < 192) {
        int t = tid >> 2, q = tid & 3;
        float4 v = ((const float4*)(x + (((long)b*T_ + t)*N_ + n)*F_))[q];
        float* dst = sm + AX + t*17 + q*4;
        dst[0] = v.x; dst[1] = v.y; dst[2] = v.z; dst[3] = v.w;
    }
    {
        const float4* src = (const float4*)g_Mh;
        float4* dst = (float4*)(sm + AM);
        dst[tid] = src[tid];
        dst[tid + 256] = src[tid + 256];
    }
    if (tid < 128) sm[AR + tid] = g_rh[tid];
    else if (tid < 256) sm[AC + tid - 128] = g_ch[tid - 128];
    if (tid < 8) sm[ACST + tid] = g_cst[tid];

    float racc[9];
    #pragma unroll
    for (int k = 0; k < 9; k++) racc[k] = 0.f;
    __syncthreads();

    const int s = tid >> 6, t64 = tid & 63;
    float* sYs = sm + AY + s*816;
    float* sSs = sm + AS + s*2352;

    for (int g = 0; g < 2; g++) {
        const int h = g*4 + s;
        // phase1: Y = X @ M_h (48x16), plus u,w vectors
        {
            int i0 = (t64 & 15)*3, c0 = (t64 >> 4)*4;
            const float* Mh = sm + AM + h*256;
            float acc[3][4] = {};
            #pragma unroll
            for (int f = 0; f < 16; f++) {
                float xv[3], mv[4];
                #pragma unroll
                for (int r = 0; r < 3; r++) xv[r] = sm[AX + (i0+r)*17 + f];
                #pragma unroll
                for (int c = 0; c < 4; c++) mv[c] = Mh[f*16 + c0 + c];
                #pragma unroll
                for (int r = 0; r < 3; r++)
                    #pragma unroll
                    for (int c = 0; c < 4; c++)
                        acc[r][c] = fmaf(xv[r], mv[c], acc[r][c]);
            }
            #pragma unroll
            for (int r = 0; r < 3; r++)
                #pragma unroll
                for (int c = 0; c < 4; c++)
                    sYs[(i0+r)*17 + c0 + c] = acc[r][c];
            if (t64 < 48) {
                int i = t64;
                float uu = 0.f, ww = sm[ACST + h];
                #pragma unroll
                for (int f = 0; f < 16; f++) {
                    float xx = sm[AX + i*17 + f];
                    uu = fmaf(sm[AR + h*16 + f], xx, uu);
                    ww = fmaf(sm[AC + h*16 + f], xx, ww);
                }
                sm[AU + s*48 + i] = uu;
                sm[AW + s*48 + i] = ww;
            }
        }
        __syncthreads();
        // phase2: S = Y @ X^T + u_i + w_j (48x48)
        {
            int ti = t64 >> 3, tj = t64 & 7;
            int i0 = ti*6, j0 = tj*6;
            float acc[6][6] = {};
            #pragma unroll
            for (int gg = 0; gg < 16; gg++) {
                float yv[6], xv[6];
                #pragma unroll
                for (int r = 0; r < 6; r++) yv[r] = sYs[(i0+r)*17 + gg];
                #pragma unroll
                for (int c = 0; c < 6; c++) xv[c] = sm[AX + (j0+c)*17 + gg];
                #pragma unroll
                for (int r = 0; r < 6; r++)
                    #pragma unroll
                    for (int c = 0; c < 6; c++)
                        acc[r][c] = fmaf(yv[r], xv[c], acc[r][c]);
            }
            #pragma unroll
            for (int r = 0; r < 6; r++) {
                float u = sm[AU + s*48 + i0 + r];
                #pragma unroll
                for (int c = 0; c < 6; c++)
                    sSs[(i0+r)*49 + j0 + c] = acc[r][c] + u + sm[AW + s*48 + j0 + c];
            }
        }
        __syncthreads();
        // phase3: softmax rows (2 warps per head, 24 rows each); alphas back into sSs
        {
            int wslot = t64 >> 5, ln = t64 & 31;
            for (int rr = 0; rr < 24; rr++) {
                int i = wslot*24 + rr;
                float v0 = sSs[i*49 + ln];
                float v1 = (ln < 16) ? sSs[i*49 + 32 + ln] : -FLT_MAX;
                float m = warp_red_max(fmaxf(v0, v1));
                float e0 = __expf(v0 - m);
                float e1 = (ln < 16) ? __expf(v1 - m) : 0.f;
                float inv = 1.f / warp_red_sum(e0 + e1);
                float a0 = e0*inv, a1 = e1*inv;
                sSs[i*49 + ln] = a0;
                if (ln < 16) sSs[i*49 + 32 + ln] = a1;
                if (i == T_-1) {
                    sm[AAL + s*48 + ln] = a0;
                    if (ln < 16) sm[AAL + s*48 + 32 + ln] = a1;
                }
            }
        }
        __syncthreads();
        // phase4: accumulate t_attn mean in registers; xbar = X^T @ alast
        #pragma unroll
        for (int k = 0; k < 9; k++) {
            int idx = k*256 + tid;          // 2304 logical (i*48+j)
            int i = idx / 48, j = idx - i*48;
            float v = 0.f;
            #pragma unroll
            for (int sl = 0; sl < 4; sl++)
                v += sm[AS + sl*2352 + i*49 + j];
            racc[k] += v;
        }
        if (t64 < 16) {
            int f = t64;
            float xb = 0.f;
            #pragma unroll
            for (int k = 0; k < 48; k++)
                xb = fmaf(sm[AAL + s*48 + k], sm[AX + k*17 + f], xb);
            sm[AXB + s*16 + f] = xb;
        }
        __syncthreads();
        // phase5: o = Wv @ xbar + bv
        if (t64 < 16) {
            int d = t64;
            int row = 256 + h*16 + d;
            float o = g_b2[row];
            #pragma unroll
            for (int f = 0; f < 16; f++)
                o = fmaf(g_W2T[f*384 + row], sm[AXB + s*16 + f], o);
            g_olast[(long)bn*H_ + h*16 + d] = o;
        }
        __syncthreads();
    }
    #pragma unroll
    for (int k = 0; k < 9; k++)
        tattn[(long)bn*2304 + k*256 + tid] = racc[k]*0.125f;
}

// ---------------- 16x128 tiled GEMM with fused epilogues ----------------
// bt=1: B is (N,K) row-major. epi: 0 none, 1 relu, 2 gelu, 3 layernorm(+res)
__global__ __launch_bounds__(256) void gemm16_kernel(
    const float* __restrict__ A, const float* __restrict__ Bm,
    const float* __restrict__ bias, float* __restrict__ C,
    int K, int lda, int ldb, int ldc, int bt, int epi,
    const float* __restrict__ res, const float* __restrict__ gw, const float* __restrict__ bw,
    long strA, long strB, long strC)
{
    A  += (long)blockIdx.z * strA;
    Bm += (long)blockIdx.z * strB;
    C  += (long)blockIdx.z * strC;
    const int rowbase = blockIdx.x * 16;
    const int colbase = blockIdx.y * 128;
    __shared__ float As[32][17];
    __shared__ float Bs[32][132];
    const int tid = threadIdx.x;
    const int tx = tid & 31, ty = tid >> 5;
    float acc[2][4] = {};
    for (int k0 = 0; k0 < K; k0 += 32) {
        #pragma unroll
        for (int it = 0; it < 2; it++) {
            int idx = tid + it*256;
            int r = idx >> 5, kk = idx & 31;
            As[kk][r] = A[(long)(rowbase + r)*lda + k0 + kk];
        }
        if (bt) {
            #pragma unroll
            for (int it = 0; it < 16; it++) {
                int idx = tid + it*256;
                int c = idx >> 5, kk = idx & 31;
                Bs[kk][c] = Bm[(long)(colbase + c)*ldb + k0 + kk];
            }
        } else {
            #pragma unroll
            for (int it = 0; it < 16; it++) {
                int idx = tid + it*256;
                int kk = idx >> 7, c = idx & 127;
                Bs[kk][c] = Bm[(long)(k0 + kk)*ldb + colbase + c];
            }
        }
        __syncthreads();
        #pragma unroll
        for (int kk = 0; kk < 32; kk++) {
            float a0 = As[kk][ty], a1 = As[kk][ty + 8];
            float bb[4];
            #pragma unroll
            for (int j = 0; j < 4; j++) bb[j] = Bs[kk][tx + 32*j];
            #pragma unroll
            for (int j = 0; j < 4; j++) {
                acc[0][j] = fmaf(a0, bb[j], acc[0][j]);
                acc[1][j] = fmaf(a1, bb[j], acc[1][j]);
            }
        }
        __syncthreads();
    }
    if (epi == 3) {
        // fused +bias +res, LayerNorm over 128 cols (colbase==0)
        #pragma unroll
        for (int i = 0; i < 2; i++) {
            int r = rowbase + ty + 8*i;
            float v[4];
            #pragma unroll
            for (int j = 0; j < 4; j++) {
                int c = tx + 32*j;
                v[j] = acc[i][j] + bias[c] + res[(long)r*128 + c];
            }
            float m = warp_red_sum(v[0]+v[1]+v[2]+v[3]) * (1.f/128.f);
            float d2 = 0.f;
            #pragma unroll
            for (int j = 0; j < 4; j++) { float d = v[j]-m; d2 += d*d; }
            float var = warp_red_sum(d2) * (1.f/128.f);
            float inv = rsqrtf(var + 1e-5f);
            #pragma unroll
            for (int j = 0; j < 4; j++) {
                int c = tx + 32*j;
                C[(long)r*ldc + c] = (v[j]-m)*inv*gw[c] + bw[c];
            }
        }
    } else {
        #pragma unroll
        for (int i = 0; i < 2; i++) {
            int r = rowbase + ty + 8*i;
            #pragma unroll
            for (int j = 0; j < 4; j++) {
                int c = colbase + tx + 32*j;
                float v = acc[i][j];
                if (bias) v += bias[c];
                if (epi == 1) v = fmaxf(v, 0.f);
                else if (epi == 2) v = 0.5f*v*(1.f + erff(v*0.70710678118654752f));
                C[(long)r*ldc + c] = v;
            }
        }
    }
}

// ---------------- s1 = gh.a1, s2 = gh.a2 ----------------
__global__ void s1s2_kernel(const float* __restrict__ gat_a)
{
    int row = blockIdx.x*8 + (threadIdx.x >> 5);
    int lane = threadIdx.x & 31;
    float p1 = 0.f, p2 = 0.f;
    #pragma unroll
    for (int u = 0; u < 4; u++) {
        int c = lane + 32*u;
        float gv = g_gh[(long)row*H_ + c];
        p1 = fmaf(gv, gat_a[c], p1);
        p2 = fmaf(gv, gat_a[H_ + c], p2);
    }
    p1 = warp_red_sum(p1); p2 = warp_red_sum(p2);
    if (lane == 0) { g_s1[row] = p1; g_s2[row] = p2; }
}

// ---------------- GAT alpha ----------------
__global__ __launch_bounds__(256) void alpha_kernel(const int* __restrict__ adj,
                                                    float* __restrict__ out_alpha)
{
    int bi = blockIdx.x;
    int b = bi >> 9, i = bi & 511;
    int tid = threadIdx.x;
    __shared__ float red[8];
    float s1v = g_s1[b*N_ + i];
    float e[2];
    float mloc = -FLT_MAX;
    #pragma unroll
    for (int u = 0; u < 2; u++) {
        int j = tid + u*256;
        float v = s1v + g_s2[b*N_ + j];
        v = (v >= 0.f) ? v : 0.2f*v;
        if (adj[i*N_ + j] == 0) v = -FLT_MAX;
        e[u] = v;
        mloc = fmaxf(mloc, v);
    }
    mloc = warp_red_max(mloc);
    if ((tid & 31) == 0) red[tid >> 5] = mloc;
    __syncthreads();
    float m = red[0];
    #pragma unroll
    for (int w = 1; w < 8; w++) m = fmaxf(m, red[w]);
    __syncthreads();
    float sloc = 0.f;
    #pragma unroll
    for (int u = 0; u < 2; u++) {
        e[u] = (e[u] == -FLT_MAX) ? 0.f : __expf(e[u] - m);
        sloc += e[u];
    }
    sloc = warp_red_sum(sloc);
    if ((tid & 31) == 0) red[tid >> 5] = sloc;
    __syncthreads();
    float ssum = red[0]+red[1]+red[2]+red[3]+red[4]+red[5]+red[6]+red[7];
    float inv = 1.f/ssum;
    #pragma unroll
    for (int u = 0; u < 2; u++)
        out_alpha[((long)(b*N_ + i))*N_ + tid + u*256] = e[u]*inv;
}

// ---------------- output heads ----------------
__global__ __launch_bounds__(128) void heads_kernel(
    const float* __restrict__ reg_w,  const float* __restrict__ reg_b,
    const float* __restrict__ risk_w, const float* __restrict__ risk_b,
    const float* __restrict__ warn_w, const float* __restrict__ warn_b,
    float* __restrict__ out)
{
    int bn = blockIdx.x;
    __shared__ float row[H_];
    int tid = threadIdx.x;
    row[tid] = g_fused[(long)bn*H_ + tid];
    __syncthreads();
    if (tid < 30) {
        const float* w; float bb; long off;
        if (tid < 6)       { w = reg_w  + tid*H_;        bb = reg_b[tid];       off = OFF_REG  + (long)bn*6  + tid; }
        else if (tid < 24) { int k = tid-6;  w = risk_w + k*H_; bb = risk_b[k]; off = OFF_RISK + (long)bn*18 + k; }
        else               { int k = tid-24; w = warn_w + k*H_; bb = warn_b[k]; off = OFF_WARN + (long)bn*6  + k; }
        float s = bb;
        #pragma unroll 8
        for (int c = 0; c < H_; c++) s = fmaf(row[c], w[c], s);
        out[off] = s;
    }
}

// ---------------- launch ----------------
extern "C" void kernel_launch(void* const* d_in, const int* in_sizes, int n_in,
                              void* d_out, int out_size)
{
    const float* x        = (const float*)d_in[0];
    const float* x_static = (const float*)d_in[1];
    const int*   adj      = (const int*)  d_in[2];
    const float* proj_w   = (const float*)d_in[3];
    const float* proj_b   = (const float*)d_in[4];
    const float* in_w     = (const float*)d_in[5];
    const float* in_b     = (const float*)d_in[6];
    const float* out_w    = (const float*)d_in[7];
    const float* out_b    = (const float*)d_in[8];
    const float* ln1_g    = (const float*)d_in[9];
    const float* ln1_b    = (const float*)d_in[10];
    const float* ffn_w1   = (const float*)d_in[11];
    const float* ffn_b1   = (const float*)d_in[12];
    const float* ffn_w2   = (const float*)d_in[13];
    const float* ffn_b2   = (const float*)d_in[14];
    const float* ln2_g    = (const float*)d_in[15];
    const float* ln2_b    = (const float*)d_in[16];
    const float* stat_w   = (const float*)d_in[17];
    const float* stat_b   = (const float*)d_in[18];
    const float* gat_w    = (const float*)d_in[19];
    const float* gat_a    = (const float*)d_in[20];
    const float* fuse_w   = (const float*)d_in[21];
    const float* fuse_b   = (const float*)d_in[22];
    const float* reg_w    = (const float*)d_in[23];
    const float* reg_b    = (const float*)d_in[24];
    const float* risk_w   = (const float*)d_in[25];
    const float* risk_b   = (const float*)d_in[26];
    const float* warn_w   = (const float*)d_in[27];
    const float* warn_b   = (const float*)d_in[28];
    float* out = (float*)d_out;

    float *p_olast, *p_hlast, *p_hln1, *p_ffn1, *p_node3, *p_gh;
    cudaGetSymbolAddress((void**)&p_olast, g_olast);
    cudaGetSymbolAddress((void**)&p_hlast, g_hlast);
    cudaGetSymbolAddress((void**)&p_hln1,  g_hln1);
    cudaGetSymbolAddress((void**)&p_ffn1,  g_ffn1);
    cudaGetSymbolAddress((void**)&p_node3, g_node3);
    cudaGetSymbolAddress((void**)&p_gh,    g_gh);
    float* p_fused; cudaGetSymbolAddress((void**)&p_fused, g_fused);

    const int ATTN2_SMEM = ATTN2_FLOATS * 4;  // 65760 bytes
    cudaFuncSetAttribute(attn2_kernel, cudaFuncAttributeMaxDynamicSharedMemorySize, ATTN2_SMEM);

    // 0-4: prep (cheap, puts attn2 at ncu launch index 5)
    prepw2_kernel<<<384, 32>>>(in_w, in_b, proj_w, proj_b);
    prep2m_kernel<<<8, 256>>>();
    prep2rc_kernel<<<8, 64>>>();
    hlast_kernel<<<BN_, 128>>>(x, proj_w, proj_b);
    srepr2_kernel<<<N_, 128>>>(x_static, stat_w, stat_b);
    // 5: attention
    attn2_kernel<<<BN_, 256, ATTN2_SMEM>>>(x, out + OFF_TATTN);

    // out-proj + LN1 fused
    gemm16_kernel<<<dim3(BN_/16,1,1),256>>>(p_olast, out_w, out_b, p_hln1,
        128, 128, 128, 128, 1, 3, p_hlast, ln1_g, ln1_b, 0, 0, 0);
    // FFN1 (gelu)
    gemm16_kernel<<<dim3(BN_/16,2,1),256>>>(p_hln1, ffn_w1, ffn_b1, p_ffn1,
        128, 128, 128, 256, 1, 2, nullptr, nullptr, nullptr, 0, 0, 0);
    // FFN2 + LN2 fused, writes t_repr directly into node3[:,0:128]
    gemm16_kernel<<<dim3(BN_/16,1,1),256>>>(p_ffn1, ffn_w2, ffn_b2, p_node3,
        256, 256, 256, 384, 1, 3, p_hln1, ln2_g, ln2_b, 0, 0, 0);
    // GAT projection gh = node[:, :256] @ gat_w^T
    gemm16_kernel<<<dim3(BN_/16,1,1),256>>>(p_node3, gat_w, nullptr, p_gh,
        256, 384, 256, 128, 1, 0, nullptr, nullptr, nullptr, 0, 0, 0);
    s1s2_kernel<<<N_, 256>>>(gat_a);
    alpha_kernel<<<BN_, 256>>>(adj, out + OFF_ALPHA);
    // g_repr = alpha @ gh -> node3[:,256:384]
    gemm16_kernel<<<dim3(N_/16,1,B_),256>>>(out + OFF_ALPHA, p_gh, nullptr,
        p_node3 + 256, 512, 512, 128, 384, 0, 0, nullptr, nullptr, nullptr,
        (long)N_*N_, (long)N_*H_, (long)N_*384);
    // fused projection (relu)
    gemm16_kernel<<<dim3(BN_/16,1,1),256>>>(p_node3, fuse_w, fuse_b, p_fused,
        384, 384, 384, 128, 1, 1, nullptr, nullptr, nullptr, 0, 0, 0);
    heads_kernel<<<BN_, 128>>>(reg_w, reg_b, risk_w, risk_b, warn_w, warn_b, out);

    (void)in_sizes; (void)n_in; (void)out_size;
}

// round 4
// speedup vs baseline: 1.3456x; 1.2115x over previous
#include <cuda_runtime.h>
#include <math.h>
#include <float.h>

#define B_ 8
#define T_ 48
#define N_ 512
#define F_ 16
#define S_ 12
#define H_ 128
#define NH_ 8
#define HZ_ 6
#define NC_ 3
#define BN_ (B_*N_)   /* 4096 */

#define OFF_REG   0L
#define OFF_RISK  24576L
#define OFF_WARN  98304L
#define OFF_TATTN 122880L
#define OFF_ALPHA 9560064L

// ---------------- scratch ----------------
__device__ __align__(16) float g_W2T[16*384];   // fused (in_w@proj_w) weight, [f][row]
__device__ __align__(16) float g_b2[384];
__device__ __align__(16) float g_Mh[8*256];     // per-head Wq^T Wk (scaled 0.25)
__device__ __align__(16) float g_rh[8*16];
__device__ __align__(16) float g_ch[8*16];
__device__ __align__(16) float g_cst[8];
__device__ __align__(16) float g_hlast[BN_*H_];
__device__ __align__(16) float g_olast[BN_*H_];
__device__ __align__(16) float g_hln1[BN_*H_];
__device__ __align__(16) float g_ffn1[BN_*2*H_];
__device__ __align__(16) float g_node3[BN_*3*H_];
__device__ __align__(16) float g_gh[BN_*H_];
__device__ __align__(16) float g_s1[BN_];
__device__ __align__(16) float g_s2[BN_];

// ---------------- helpers ----------------
__device__ __forceinline__ float warp_red_sum(float v) {
    #pragma unroll
    for (int o = 16; o > 0; o >>= 1) v += __shfl_xor_sync(0xffffffffu, v, o);
    return v;
}
__device__ __forceinline__ float warp_red_max(float v) {
    #pragma unroll
    for (int o = 16; o > 0; o >>= 1) v = fmaxf(v, __shfl_xor_sync(0xffffffffu, v, o));
    return v;
}

// ---------------- W2 = in_w @ proj_w ; b2 = in_w @ proj_b + in_b ----------------
__global__ void prepw2_kernel(const float* __restrict__ in_w, const float* __restrict__ in_b,
                              const float* __restrict__ proj_w, const float* __restrict__ proj_b)
{
    int j = blockIdx.x;            // 0..383
    int lane = threadIdx.x;        // 32
    float wreg[4];
    #pragma unroll
    for (int u = 0; u < 4; u++) wreg[u] = in_w[j*H_ + lane + 32*u];
    float pb = 0.f;
    #pragma unroll
    for (int u = 0; u < 4; u++) pb += wreg[u] * proj_b[lane + 32*u];
    pb = warp_red_sum(pb);
    if (lane == 0) g_b2[j] = pb + in_b[j];
    for (int f = 0; f < 16; f++) {
        float s = 0.f;
        #pragma unroll
        for (int u = 0; u < 4; u++) s += wreg[u] * proj_w[(lane + 32*u)*16 + f];
        s = warp_red_sum(s);
        if (lane == 0) g_W2T[f*384 + j] = s;
    }
}

// ---------------- per-head score matrices ----------------
__global__ __launch_bounds__(256) void prep2m_kernel()
{
    int h = blockIdx.x;
    int f = threadIdx.x >> 4, g = threadIdx.x & 15;
    float s = 0.f;
    #pragma unroll
    for (int d = 0; d < 16; d++)
        s = fmaf(g_W2T[f*384 + h*16 + d], g_W2T[g*384 + 128 + h*16 + d], s);
    g_Mh[h*256 + f*16 + g] = 0.25f*s;
}
__global__ void prep2rc_kernel()
{
    int h = blockIdx.x, tid = threadIdx.x;
    if (tid < 16) {
        float s = 0.f;
        #pragma unroll
        for (int d = 0; d < 16; d++)
            s = fmaf(g_W2T[tid*384 + h*16 + d], g_b2[128 + h*16 + d], s);
        g_rh[h*16 + tid] = 0.25f*s;
    } else if (tid < 32) {
        int g = tid - 16;
        float s = 0.f;
        #pragma unroll
        for (int d = 0; d < 16; d++)
            s = fmaf(g_b2[h*16 + d], g_W2T[g*384 + 128 + h*16 + d], s);
        g_ch[h*16 + g] = 0.25f*s;
    } else if (tid == 32) {
        float s = 0.f;
        #pragma unroll
        for (int d = 0; d < 16; d++)
            s = fmaf(g_b2[h*16 + d], g_b2[128 + h*16 + d], s);
        g_cst[h] = 0.25f*s;
    }
}

// ---------------- attention v3 (+hlast +srepr folded) ----------------
// smem floats:
#define AX   0        /* 48*17 = 816 */
#define AY   816      /* 4*816 = 3264 */
#define AS   4080     /* 4*2352 = 9408 */
#define AU   13488    /* 192 */
#define AW   13680    /* 192 */
#define AXB  13872    /* 64 */
#define ATTN3_FLOATS 13936

__global__ __launch_bounds__(256,4) void attn3_kernel(const float* __restrict__ x,
    const float* __restrict__ proj_w, const float* __restrict__ proj_b,
    const float* __restrict__ x_static, const float* __restrict__ stat_w,
    const float* __restrict__ stat_b,
    float* __restrict__ tattn)
{
    extern __shared__ float sm[];
    const int bn = blockIdx.x;
    const int b = bn >> 9, n = bn & 511;
    const int tid = threadIdx.x;

    // load x tile (48x16) -> sX padded 17
    if (tid < 192) {
        int t = tid >> 2, q = tid & 3;
        float4 v = ((const float4*)(x + (((long)b*T_ + t)*N_ + n)*F_))[q];
        float* dst = sm + AX + t*17 + q*4;
        dst[0] = v.x; dst[1] = v.y; dst[2] = v.z; dst[3] = v.w;
    }
    float racc[9];
    #pragma unroll
    for (int k = 0; k < 9; k++) racc[k] = 0.f;
    __syncthreads();

    const int s = tid >> 6, t64 = tid & 63;
    float* sYs = sm + AY + s*816;
    float* sSs = sm + AS + s*2352;

    #pragma unroll
    for (int g = 0; g < 2; g++) {
        const int h = g*4 + s;
        // phase1: Y = X @ M_h (48x16) + u,w vectors; M/r/c from global (L1/L2 resident)
        {
            int i0 = (t64 & 15)*3, q4 = (t64 >> 4);   // q4 in 0..3, cols 4*q4..
            const float4* M4 = (const float4*)(g_Mh + h*256) + q4;
            float acc[3][4] = {};
            #pragma unroll
            for (int f = 0; f < 16; f++) {
                float4 mv = M4[f*4];
                float xv[3];
                #pragma unroll
                for (int r = 0; r < 3; r++) xv[r] = sm[AX + (i0+r)*17 + f];
                #pragma unroll
                for (int r = 0; r < 3; r++) {
                    acc[r][0] = fmaf(xv[r], mv.x, acc[r][0]);
                    acc[r][1] = fmaf(xv[r], mv.y, acc[r][1]);
                    acc[r][2] = fmaf(xv[r], mv.z, acc[r][2]);
                    acc[r][3] = fmaf(xv[r], mv.w, acc[r][3]);
                }
            }
            #pragma unroll
            for (int r = 0; r < 3; r++)
                #pragma unroll
                for (int c = 0; c < 4; c++)
                    sYs[(i0+r)*17 + q4*4 + c] = acc[r][c];
            if (t64 < 48) {
                int i = t64;
                float uu = 0.f, ww = g_cst[h];
                #pragma unroll
                for (int f = 0; f < 16; f++) {
                    float xx = sm[AX + i*17 + f];
                    uu = fmaf(g_rh[h*16 + f], xx, uu);
                    ww = fmaf(g_ch[h*16 + f], xx, ww);
                }
                sm[AU + s*48 + i] = uu;
                sm[AW + s*48 + i] = ww;
            }
        }
        __syncthreads();
        // phase2: S = Y @ X^T + u_i + w_j (48x48)
        {
            int ti = t64 >> 3, tj = t64 & 7;
            int i0 = ti*6, j0 = tj*6;
            float acc[6][6] = {};
            #pragma unroll
            for (int gg = 0; gg < 16; gg++) {
                float yv[6], xv[6];
                #pragma unroll
                for (int r = 0; r < 6; r++) yv[r] = sYs[(i0+r)*17 + gg];
                #pragma unroll
                for (int c = 0; c < 6; c++) xv[c] = sm[AX + (j0+c)*17 + gg];
                #pragma unroll
                for (int r = 0; r < 6; r++)
                    #pragma unroll
                    for (int c = 0; c < 6; c++)
                        acc[r][c] = fmaf(yv[r], xv[c], acc[r][c]);
            }
            #pragma unroll
            for (int r = 0; r < 6; r++) {
                float u = sm[AU + s*48 + i0 + r];
                #pragma unroll
                for (int c = 0; c < 6; c++)
                    sSs[(i0+r)*49 + j0 + c] = acc[r][c] + u + sm[AW + s*48 + j0 + c];
            }
        }
        __syncthreads();
        // phase3: softmax, one thread per row (192 threads)
        if (tid < 192) {
            int s3 = tid / 48, i = tid - s3*48;
            float* row = sm + AS + s3*2352 + i*49;
            float m = -FLT_MAX;
            #pragma unroll
            for (int j = 0; j < 48; j++) m = fmaxf(m, row[j]);
            float ssum = 0.f;
            #pragma unroll
            for (int j = 0; j < 48; j++) {
                float e = __expf(row[j] - m);
                row[j] = e;
                ssum += e;
            }
            float inv = 1.f/ssum;
            #pragma unroll
            for (int j = 0; j < 48; j++) row[j] *= inv;
        }
        __syncthreads();
        // phase4: accumulate t_attn mean in regs; xbar = X^T @ alpha[47]
        #pragma unroll
        for (int k = 0; k < 9; k++) {
            int idx = k*256 + tid;          // i*48+j
            int i = idx / 48, j = idx - i*48;
            float v = 0.f;
            #pragma unroll
            for (int sl = 0; sl < 4; sl++)
                v += sm[AS + sl*2352 + i*49 + j];
            racc[k] += v;
        }
        if (t64 < 16) {
            int f = t64;
            float xb = 0.f;
            #pragma unroll
            for (int k = 0; k < 48; k++)
                xb = fmaf(sSs[47*49 + k], sm[AX + k*17 + f], xb);
            sm[AXB + s*16 + f] = xb;
        }
        __syncthreads();
        // phase5: o = Wv @ xbar + bv
        if (t64 < 16) {
            int d = t64;
            int row = 256 + h*16 + d;
            float o = g_b2[row];
            #pragma unroll
            for (int f = 0; f < 16; f++)
                o = fmaf(g_W2T[f*384 + row], sm[AXB + s*16 + f], o);
            g_olast[(long)bn*H_ + h*16 + d] = o;
        }
        __syncthreads();
    }
    #pragma unroll
    for (int k = 0; k < 9; k++)
        tattn[(long)bn*2304 + k*256 + tid] = racc[k]*0.125f;

    // folded hlast: h(T-1) = proj_w @ x_last + proj_b
    if (tid < 128) {
        float hsum = proj_b[tid];
        const float4* pw = (const float4*)(proj_w + tid*16);
        #pragma unroll
        for (int q = 0; q < 4; q++) {
            float4 w4 = pw[q];
            hsum = fmaf(w4.x, sm[AX + 47*17 + q*4 + 0], hsum);
            hsum = fmaf(w4.y, sm[AX + 47*17 + q*4 + 1], hsum);
            hsum = fmaf(w4.z, sm[AX + 47*17 + q*4 + 2], hsum);
            hsum = fmaf(w4.w, sm[AX + 47*17 + q*4 + 3], hsum);
        }
        g_hlast[(long)bn*H_ + tid] = hsum;
    }
    // folded s_repr (only b==0 blocks): relu(x_static @ stat_w^T + stat_b) -> node3[:,128:256]
    if (bn < 512 && tid < 128) {
        float v = stat_b[tid];
        #pragma unroll
        for (int f = 0; f < S_; f++)
            v = fmaf(x_static[n*S_ + f], stat_w[tid*S_ + f], v);
        v = fmaxf(v, 0.f);
        #pragma unroll
        for (int bb = 0; bb < B_; bb++)
            g_node3[((long)(bb*N_ + n))*384 + 128 + tid] = v;
    }
}

// ---------------- 16x128 tiled GEMM with fused epilogues ----------------
// bt=1: B is (N,K) row-major. epi: 0 none, 1 relu, 2 gelu, 3 LN(+res),
// 4 = write C + s1/s2 dots with ga, 5 = relu + head projections (no C write)
__global__ __launch_bounds__(256) void gemm16_kernel(
    const float* __restrict__ A, const float* __restrict__ Bm,
    const float* __restrict__ bias, float* __restrict__ C,
    int K, int lda, int ldb, int ldc, int bt, int epi,
    const float* __restrict__ res, const float* __restrict__ gw, const float* __restrict__ bw,
    const float* __restrict__ ga, float* __restrict__ s1o, float* __restrict__ s2o,
    const float* __restrict__ hwreg, const float* __restrict__ hbreg,
    const float* __restrict__ hwrisk, const float* __restrict__ hbrisk,
    const float* __restrict__ hwwarn, const float* __restrict__ hbwarn,
    float* __restrict__ hout,
    long strA, long strB, long strC)
{
    A  += (long)blockIdx.z * strA;
    Bm += (long)blockIdx.z * strB;
    C  += (long)blockIdx.z * strC;
    const int rowbase = blockIdx.x * 16;
    const int colbase = blockIdx.y * 128;
    __shared__ float As[32][17];
    __shared__ float Bs[32][132];
    const int tid = threadIdx.x;
    const int tx = tid & 31, ty = tid >> 5;
    float acc[2][4] = {};
    for (int k0 = 0; k0 < K; k0 += 32) {
        #pragma unroll
        for (int it = 0; it < 2; it++) {
            int idx = tid + it*256;
            int r = idx >> 5, kk = idx & 31;
            As[kk][r] = A[(long)(rowbase + r)*lda + k0 + kk];
        }
        if (bt) {
            #pragma unroll
            for (int it = 0; it < 16; it++) {
                int idx = tid + it*256;
                int c = idx >> 5, kk = idx & 31;
                Bs[kk][c] = Bm[(long)(colbase + c)*ldb + k0 + kk];
            }
        } else {
            #pragma unroll
            for (int it = 0; it < 16; it++) {
                int idx = tid + it*256;
                int kk = idx >> 7, c = idx & 127;
                Bs[kk][c] = Bm[(long)(k0 + kk)*ldb + colbase + c];
            }
        }
        __syncthreads();
        #pragma unroll
        for (int kk = 0; kk < 32; kk++) {
            float a0 = As[kk][ty], a1 = As[kk][ty + 8];
            float bb[4];
            #pragma unroll
            for (int j = 0; j < 4; j++) bb[j] = Bs[kk][tx + 32*j];
            #pragma unroll
            for (int j = 0; j < 4; j++) {
                acc[0][j] = fmaf(a0, bb[j], acc[0][j]);
                acc[1][j] = fmaf(a1, bb[j], acc[1][j]);
            }
        }
        __syncthreads();
    }
    if (epi == 3) {
        #pragma unroll
        for (int i = 0; i < 2; i++) {
            int r = rowbase + ty + 8*i;
            float v[4];
            #pragma unroll
            for (int j = 0; j < 4; j++) {
                int c = tx + 32*j;
                v[j] = acc[i][j] + bias[c] + res[(long)r*128 + c];
            }
            float m = warp_red_sum(v[0]+v[1]+v[2]+v[3]) * (1.f/128.f);
            float d2 = 0.f;
            #pragma unroll
            for (int j = 0; j < 4; j++) { float d = v[j]-m; d2 += d*d; }
            float var = warp_red_sum(d2) * (1.f/128.f);
            float inv = rsqrtf(var + 1e-5f);
            #pragma unroll
            for (int j = 0; j < 4; j++) {
                int c = tx + 32*j;
                C[(long)r*ldc + c] = (v[j]-m)*inv*gw[c] + bw[c];
            }
        }
    } else if (epi == 4) {
        #pragma unroll
        for (int i = 0; i < 2; i++) {
            int r = rowbase + ty + 8*i;
            float p1 = 0.f, p2 = 0.f;
            #pragma unroll
            for (int j = 0; j < 4; j++) {
                int c = tx + 32*j;
                float v = acc[i][j];
                C[(long)r*ldc + c] = v;
                p1 = fmaf(v, ga[c], p1);
                p2 = fmaf(v, ga[128 + c], p2);
            }
            p1 = warp_red_sum(p1);
            p2 = warp_red_sum(p2);
            if (tx == 0) { s1o[r] = p1; s2o[r] = p2; }
        }
    } else if (epi == 5) {
        // relu into Bs[0..15][c], then 30 head dots per row
        #pragma unroll
        for (int i = 0; i < 2; i++)
            #pragma unroll
            for (int j = 0; j < 4; j++)
                Bs[ty + 8*i][tx + 32*j] = fmaxf(acc[i][j] + bias[tx + 32*j], 0.f);
        __syncthreads();
        for (int p = tid; p < 480; p += 256) {
            int r = p / 30, o = p - 30*r;
            const float* w; float bb; long off;
            if (o < 6)       { w = hwreg  + o*H_;        bb = hbreg[o];        off = OFF_REG  + (long)(rowbase+r)*6  + o; }
            else if (o < 24) { int k = o-6;  w = hwrisk + k*H_; bb = hbrisk[k]; off = OFF_RISK + (long)(rowbase+r)*18 + k; }
            else             { int k = o-24; w = hwwarn + k*H_; bb = hbwarn[k]; off = OFF_WARN + (long)(rowbase+r)*6  + k; }
            float sacc = bb;
            #pragma unroll 8
            for (int c = 0; c < H_; c++)
                sacc = fmaf(Bs[r][c], w[c], sacc);
            hout[off] = sacc;
        }
    } else {
        #pragma unroll
        for (int i = 0; i < 2; i++) {
            int r = rowbase + ty + 8*i;
            #pragma unroll
            for (int j = 0; j < 4; j++) {
                int c = colbase + tx + 32*j;
                float v = acc[i][j];
                if (bias) v += bias[c];
                if (epi == 1) v = fmaxf(v, 0.f);
                else if (epi == 2) v = 0.5f*v*(1.f + erff(v*0.70710678118654752f));
                C[(long)r*ldc + c] = v;
            }
        }
    }
}

// ---------------- GAT alpha ----------------
__global__ __launch_bounds__(256) void alpha_kernel(const int* __restrict__ adj,
                                                    float* __restrict__ out_alpha)
{
    int bi = blockIdx.x;
    int b = bi >> 9, i = bi & 511;
    int tid = threadIdx.x;
    __shared__ float red[8];
    float s1v = g_s1[b*N_ + i];
    float e[2];
    float mloc = -FLT_MAX;
    #pragma unroll
    for (int u = 0; u < 2; u++) {
        int j = tid + u*256;
        float v = s1v + g_s2[b*N_ + j];
        v = (v >= 0.f) ? v : 0.2f*v;
        if (adj[i*N_ + j] == 0) v = -FLT_MAX;
        e[u] = v;
        mloc = fmaxf(mloc, v);
    }
    mloc = warp_red_max(mloc);
    if ((tid & 31) == 0) red[tid >> 5] = mloc;
    __syncthreads();
    float m = red[0];
    #pragma unroll
    for (int w = 1; w < 8; w++) m = fmaxf(m, red[w]);
    __syncthreads();
    float sloc = 0.f;
    #pragma unroll
    for (int u = 0; u < 2; u++) {
        e[u] = (e[u] == -FLT_MAX) ? 0.f : __expf(e[u] - m);
        sloc += e[u];
    }
    sloc = warp_red_sum(sloc);
    if ((tid & 31) == 0) red[tid >> 5] = sloc;
    __syncthreads();
    float ssum = red[0]+red[1]+red[2]+red[3]+red[4]+red[5]+red[6]+red[7];
    float inv = 1.f/ssum;
    #pragma unroll
    for (int u = 0; u < 2; u++)
        out_alpha[((long)(b*N_ + i))*N_ + tid + u*256] = e[u]*inv;
}

// ---------------- launch ----------------
extern "C" void kernel_launch(void* const* d_in, const int* in_sizes, int n_in,
                              void* d_out, int out_size)
{
    const float* x        = (const float*)d_in[0];
    const float* x_static = (const float*)d_in[1];
    const int*   adj      = (const int*)  d_in[2];
    const float* proj_w   = (const float*)d_in[3];
    const float* proj_b   = (const float*)d_in[4];
    const float* in_w     = (const float*)d_in[5];
    const float* in_b     = (const float*)d_in[6];
    const float* out_w    = (const float*)d_in[7];
    const float* out_b    = (const float*)d_in[8];
    const float* ln1_g    = (const float*)d_in[9];
    const float* ln1_b    = (const float*)d_in[10];
    const float* ffn_w1   = (const float*)d_in[11];
    const float* ffn_b1   = (const float*)d_in[12];
    const float* ffn_w2   = (const float*)d_in[13];
    const float* ffn_b2   = (const float*)d_in[14];
    const float* ln2_g    = (const float*)d_in[15];
    const float* ln2_b    = (const float*)d_in[16];
    const float* stat_w   = (const float*)d_in[17];
    const float* stat_b   = (const float*)d_in[18];
    const float* gat_w    = (const float*)d_in[19];
    const float* gat_a    = (const float*)d_in[20];
    const float* fuse_w   = (const float*)d_in[21];
    const float* fuse_b   = (const float*)d_in[22];
    const float* reg_w    = (const float*)d_in[23];
    const float* reg_b    = (const float*)d_in[24];
    const float* risk_w   = (const float*)d_in[25];
    const float* risk_b   = (const float*)d_in[26];
    const float* warn_w   = (const float*)d_in[27];
    const float* warn_b   = (const float*)d_in[28];
    float* out = (float*)d_out;

    float *p_olast, *p_hlast, *p_hln1, *p_ffn1, *p_node3, *p_gh, *p_s1, *p_s2;
    cudaGetSymbolAddress((void**)&p_olast, g_olast);
    cudaGetSymbolAddress((void**)&p_hlast, g_hlast);
    cudaGetSymbolAddress((void**)&p_hln1,  g_hln1);
    cudaGetSymbolAddress((void**)&p_ffn1,  g_ffn1);
    cudaGetSymbolAddress((void**)&p_node3, g_node3);
    cudaGetSymbolAddress((void**)&p_gh,    g_gh);
    cudaGetSymbolAddress((void**)&p_s1,    g_s1);
    cudaGetSymbolAddress((void**)&p_s2,    g_s2);

    const int ATTN3_SMEM = ATTN3_FLOATS * 4;  // 55744 bytes
    cudaFuncSetAttribute(attn3_kernel, cudaFuncAttributeMaxDynamicSharedMemorySize, ATTN3_SMEM);

    // 0-2: prep
    prepw2_kernel<<<384, 32>>>(in_w, in_b, proj_w, proj_b);
    prep2m_kernel<<<8, 256>>>();
    prep2rc_kernel<<<8, 64>>>();
    // 3: attention (+hlast +srepr)
    attn3_kernel<<<BN_, 256, ATTN3_SMEM>>>(x, proj_w, proj_b, x_static, stat_w, stat_b,
                                           out + OFF_TATTN);

    // out-proj + LN1 fused
    gemm16_kernel<<<dim3(BN_/16,1,1),256>>>(p_olast, out_w, out_b, p_hln1,
        128, 128, 128, 128, 1, 3, p_hlast, ln1_g, ln1_b,
        nullptr, nullptr, nullptr, nullptr, nullptr, nullptr, nullptr, nullptr, nullptr, nullptr,
        0, 0, 0);
    // FFN1 (gelu)
    gemm16_kernel<<<dim3(BN_/16,2,1),256>>>(p_hln1, ffn_w1, ffn_b1, p_ffn1,
        128, 128, 128, 256, 1, 2, nullptr, nullptr, nullptr,
        nullptr, nullptr, nullptr, nullptr, nullptr, nullptr, nullptr, nullptr, nullptr, nullptr,
        0, 0, 0);
    // FFN2 + LN2 fused -> node3[:,0:128]
    gemm16_kernel<<<dim3(BN_/16,1,1),256>>>(p_ffn1, ffn_w2, ffn_b2, p_node3,
        256, 256, 256, 384, 1, 3, p_hln1, ln2_g, ln2_b,
        nullptr, nullptr, nullptr, nullptr, nullptr, nullptr, nullptr, nullptr, nullptr, nullptr,
        0, 0, 0);
    // gh = node[:, :256] @ gat_w^T  (+ fused s1/s2)
    gemm16_kernel<<<dim3(BN_/16,1,1),256>>>(p_node3, gat_w, nullptr, p_gh,
        256, 384, 256, 128, 1, 4, nullptr, nullptr, nullptr,
        gat_a, p_s1, p_s2, nullptr, nullptr, nullptr, nullptr, nullptr, nullptr, nullptr,
        0, 0, 0);
    alpha_kernel<<<BN_, 256>>>(adj, out + OFF_ALPHA);
    // g_repr = alpha @ gh -> node3[:,256:384]
    gemm16_kernel<<<dim3(N_/16,1,B_),256>>>(out + OFF_ALPHA, p_gh, nullptr,
        p_node3 + 256, 512, 512, 128, 384, 0, 0, nullptr, nullptr, nullptr,
        nullptr, nullptr, nullptr, nullptr, nullptr, nullptr, nullptr, nullptr, nullptr, nullptr,
        (long)N_*N_, (long)N_*H_, (long)N_*384);
    // fused projection (relu) + heads, writes reg/risk/warn directly
    gemm16_kernel<<<dim3(BN_/16,1,1),256>>>(p_node3, fuse_w, fuse_b, nullptr,
        384, 384, 384, 128, 1, 5, nullptr, nullptr, nullptr,
        nullptr, nullptr, nullptr,
        reg_w, reg_b, risk_w, risk_b, warn_w, warn_b, out,
        0, 0, 0);

    (void)in_sizes; (void)n_in; (void)out_size;
}

// round 9
// speedup vs baseline: 1.4744x; 1.0957x over previous
#include <cuda_runtime.h>
#include <math.h>
#include <float.h>

#define B_ 8
#define T_ 48
#define N_ 512
#define F_ 16
#define S_ 12
#define H_ 128
#define NH_ 8
#define HZ_ 6
#define NC_ 3
#define BN_ (B_*N_)   /* 4096 */

#define OFF_REG   0L
#define OFF_RISK  24576L
#define OFF_WARN  98304L
#define OFF_TATTN 122880L
#define OFF_ALPHA 9560064L

// ---------------- scratch ----------------
__device__ __align__(16) float g_W2T[16*384];   // fused (in_w@proj_w) weight, [f][row]
__device__ __align__(16) float g_b2[384];
__device__ __align__(16) float g_Mh[8*256];     // per-head Wq^T Wk (scaled 0.25)
__device__ __align__(16) float g_rh[8*16];
__device__ __align__(16) float g_ch[8*16];
__device__ __align__(16) float g_cst[8];
__device__ __align__(16) float g_hlast[BN_*H_];
__device__ __align__(16) float g_olast[BN_*H_];
__device__ __align__(16) float g_hln1[BN_*H_];
__device__ __align__(16) float g_ffn1[BN_*2*H_];
__device__ __align__(16) float g_node3[BN_*3*H_];
__device__ __align__(16) float g_gh[BN_*H_];
__device__ __align__(16) float g_s1[BN_];
__device__ __align__(16) float g_s2[BN_];

// ---------------- helpers ----------------
__device__ __forceinline__ float warp_red_sum(float v) {
    #pragma unroll
    for (int o = 16; o > 0; o >>= 1) v += __shfl_xor_sync(0xffffffffu, v, o);
    return v;
}
__device__ __forceinline__ float warp_red_max(float v) {
    #pragma unroll
    for (int o = 16; o > 0; o >>= 1) v = fmaxf(v, __shfl_xor_sync(0xffffffffu, v, o));
    return v;
}

// ---------------- W2 = in_w @ proj_w ; b2 = in_w @ proj_b + in_b ----------------
__global__ void prepw2_kernel(const float* __restrict__ in_w, const float* __restrict__ in_b,
                              const float* __restrict__ proj_w, const float* __restrict__ proj_b)
{
    int j = blockIdx.x;            // 0..383
    int lane = threadIdx.x;        // 32
    float wreg[4];
    #pragma unroll
    for (int u = 0; u < 4; u++) wreg[u] = in_w[j*H_ + lane + 32*u];
    float pb = 0.f;
    #pragma unroll
    for (int u = 0; u < 4; u++) pb += wreg[u] * proj_b[lane + 32*u];
    pb = warp_red_sum(pb);
    if (lane == 0) g_b2[j] = pb + in_b[j];
    for (int f = 0; f < 16; f++) {
        float s = 0.f;
        #pragma unroll
        for (int u = 0; u < 4; u++) s += wreg[u] * proj_w[(lane + 32*u)*16 + f];
        s = warp_red_sum(s);
        if (lane == 0) g_W2T[f*384 + j] = s;
    }
}

// ---------------- per-head score matrices ----------------
__global__ __launch_bounds__(256) void prep2m_kernel()
{
    int h = blockIdx.x;
    int f = threadIdx.x >> 4, g = threadIdx.x & 15;
    float s = 0.f;
    #pragma unroll
    for (int d = 0; d < 16; d++)
        s = fmaf(g_W2T[f*384 + h*16 + d], g_W2T[g*384 + 128 + h*16 + d], s);
    g_Mh[h*256 + f*16 + g] = 0.25f*s;
}
__global__ void prep2rc_kernel()
{
    int h = blockIdx.x, tid = threadIdx.x;
    if (tid < 16) {
        float s = 0.f;
        #pragma unroll
        for (int d = 0; d < 16; d++)
            s = fmaf(g_W2T[tid*384 + h*16 + d], g_b2[128 + h*16 + d], s);
        g_rh[h*16 + tid] = 0.25f*s;
    } else if (tid < 32) {
        int g = tid - 16;
        float s = 0.f;
        #pragma unroll
        for (int d = 0; d < 16; d++)
            s = fmaf(g_b2[h*16 + d], g_W2T[g*384 + 128 + h*16 + d], s);
        g_ch[h*16 + g] = 0.25f*s;
    } else if (tid == 32) {
        float s = 0.f;
        #pragma unroll
        for (int d = 0; d < 16; d++)
            s = fmaf(g_b2[h*16 + d], g_b2[128 + h*16 + d], s);
        g_cst[h] = 0.25f*s;
    }
}

// ---------------- attention v4: float4 smem + register softmax ----------------
#define XS 20
#define YS 16
#define SSL 52
#define AX   0        /* 48*20 = 960 */
#define AY   960      /* 4*48*16 = 3072 */
#define AS   4032     /* 4*48*52 = 9984 */
#define AU   14016    /* 192 */
#define AW   14208    /* 192 */
#define AXB  14400    /* 64 */
#define ATTN4_FLOATS 14464

__global__ __launch_bounds__(256,3) void attn4_kernel(const float* __restrict__ x,
    const float* __restrict__ proj_w, const float* __restrict__ proj_b,
    const float* __restrict__ x_static, const float* __restrict__ stat_w,
    const float* __restrict__ stat_b,
    float* __restrict__ tattn)
{
    extern __shared__ float sm[];
    const int bn = blockIdx.x;
    const int b = bn >> 9, n = bn & 511;
    const int tid = threadIdx.x;

    // load x tile (48x16) -> sX stride 20
    if (tid < 192) {
        int t = tid >> 2, q = tid & 3;
        float4 v = ((const float4*)(x + (((long)b*T_ + t)*N_ + n)*F_))[q];
        *(float4*)&sm[AX + t*XS + q*4] = v;
    }
    float racc[12];
    #pragma unroll
    for (int k = 0; k < 12; k++) racc[k] = 0.f;
    __syncthreads();

    const int s = tid >> 6, t64 = tid & 63;
    float* sYs = sm + AY + s*768;
    float* sSs = sm + AS + s*2496;

    for (int g = 0; g < 2; g++) {
        const int h = g*4 + s;
        // ---- phase1: Y = X @ M_h (48x16); u,w vectors ----
        {
            int i0 = (t64 & 15)*3, q4 = t64 >> 4;
            const float4* M4 = (const float4*)(g_Mh + h*256) + q4;  // M row f: M4[f*4]
            float acc[3][4] = {};
            #pragma unroll
            for (int f4 = 0; f4 < 4; f4++) {
                float xr[3][4];
                #pragma unroll
                for (int r = 0; r < 3; r++)
                    *(float4*)xr[r] = *(const float4*)&sm[AX + (i0+r)*XS + f4*4];
                #pragma unroll
                for (int u = 0; u < 4; u++) {
                    float4 mv = M4[(f4*4+u)*4];
                    #pragma unroll
                    for (int r = 0; r < 3; r++) {
                        acc[r][0] = fmaf(xr[r][u], mv.x, acc[r][0]);
                        acc[r][1] = fmaf(xr[r][u], mv.y, acc[r][1]);
                        acc[r][2] = fmaf(xr[r][u], mv.z, acc[r][2]);
                        acc[r][3] = fmaf(xr[r][u], mv.w, acc[r][3]);
                    }
                }
            }
            #pragma unroll
            for (int r = 0; r < 3; r++)
                *(float4*)&sYs[(i0+r)*YS + q4*4] =
                    make_float4(acc[r][0], acc[r][1], acc[r][2], acc[r][3]);
            if (t64 < 48) {
                int i = t64;
                float uu = 0.f, ww = g_cst[h];
                const float4* rh4 = (const float4*)(g_rh + h*16);
                const float4* ch4 = (const float4*)(g_ch + h*16);
                #pragma unroll
                for (int q = 0; q < 4; q++) {
                    float xv[4];
                    *(float4*)xv = *(const float4*)&sm[AX + i*XS + q*4];
                    float4 rv = rh4[q], cv = ch4[q];
                    uu = fmaf(rv.x, xv[0], uu); uu = fmaf(rv.y, xv[1], uu);
                    uu = fmaf(rv.z, xv[2], uu); uu = fmaf(rv.w, xv[3], uu);
                    ww = fmaf(cv.x, xv[0], ww); ww = fmaf(cv.y, xv[1], ww);
                    ww = fmaf(cv.z, xv[2], ww); ww = fmaf(cv.w, xv[3], ww);
                }
                sm[AU + s*48 + i] = uu;
                sm[AW + s*48 + i] = ww;
            }
        }
        __syncthreads();
        // ---- phase2: S tile in registers + register softmax ----
        {
            int ti = t64 >> 3, tj = t64 & 7;
            int i0 = ti*6, j0 = tj*6;
            float acc[6][6] = {};
            #pragma unroll
            for (int k4 = 0; k4 < 4; k4++) {
                float yv[6][4];
                #pragma unroll
                for (int r = 0; r < 6; r++)
                    *(float4*)yv[r] = *(const float4*)&sYs[(i0+r)*YS + k4*4];
                #pragma unroll
                for (int c = 0; c < 6; c++) {
                    float xc[4];
                    *(float4*)xc = *(const float4*)&sm[AX + (j0+c)*XS + k4*4];
                    #pragma unroll
                    for (int r = 0; r < 6; r++) {
                        acc[r][c] = fmaf(yv[r][0], xc[0], acc[r][c]);
                        acc[r][c] = fmaf(yv[r][1], xc[1], acc[r][c]);
                        acc[r][c] = fmaf(yv[r][2], xc[2], acc[r][c]);
                        acc[r][c] = fmaf(yv[r][3], xc[3], acc[r][c]);
                    }
                }
            }
            float wv[6];
            #pragma unroll
            for (int c = 0; c < 6; c++) wv[c] = sm[AW + s*48 + j0 + c];
            #pragma unroll
            for (int r = 0; r < 6; r++) {
                float uu = sm[AU + s*48 + i0 + r];
                #pragma unroll
                for (int c = 0; c < 6; c++) acc[r][c] += uu + wv[c];
            }
            // softmax per row: reduce across the 8-lane tj segment
            #pragma unroll
            for (int r = 0; r < 6; r++) {
                float m = acc[r][0];
                #pragma unroll
                for (int c = 1; c < 6; c++) m = fmaxf(m, acc[r][c]);
                m = fmaxf(m, __shfl_xor_sync(0xffffffffu, m, 1));
                m = fmaxf(m, __shfl_xor_sync(0xffffffffu, m, 2));
                m = fmaxf(m, __shfl_xor_sync(0xffffffffu, m, 4));
                float rs = 0.f;
                #pragma unroll
                for (int c = 0; c < 6; c++) {
                    float e = __expf(acc[r][c] - m);
                    acc[r][c] = e;
                    rs += e;
                }
                rs += __shfl_xor_sync(0xffffffffu, rs, 1);
                rs += __shfl_xor_sync(0xffffffffu, rs, 2);
                rs += __shfl_xor_sync(0xffffffffu, rs, 4);
                float inv = 1.f/rs;
                #pragma unroll
                for (int c = 0; c < 6; c++)
                    sSs[(i0+r)*SSL + j0 + c] = acc[r][c]*inv;
            }
        }
        __syncthreads();
        // ---- phase4: t_attn partial (float4) + xbar ----
        if (tid < 192) {
            #pragma unroll
            for (int q = 0; q < 3; q++) {
                int v = tid + q*192;
                int row = v / 12, c4 = v - row*12;
                int off = AS + row*SSL + c4*4;
                float4 a0 = *(const float4*)&sm[off];
                float4 a1 = *(const float4*)&sm[off + 2496];
                float4 a2 = *(const float4*)&sm[off + 2*2496];
                float4 a3 = *(const float4*)&sm[off + 3*2496];
                racc[q*4+0] += a0.x + a1.x + a2.x + a3.x;
                racc[q*4+1] += a0.y + a1.y + a2.y + a3.y;
                racc[q*4+2] += a0.z + a1.z + a2.z + a3.z;
                racc[q*4+3] += a0.w + a1.w + a2.w + a3.w;
            }
        }
        if (t64 < 16) {
            int f = t64;
            float xb = 0.f;
            #pragma unroll
            for (int k = 0; k < 48; k++)
                xb = fmaf(sSs[47*SSL + k], sm[AX + k*XS + f], xb);
            sm[AXB + s*16 + f] = xb;
        }
        __syncthreads();
        // ---- phase5: o = Wv @ xbar + bv ----
        if (t64 < 16) {
            int d = t64;
            int row = 256 + h*16 + d;
            float o = g_b2[row];
            #pragma unroll
            for (int f = 0; f < 16; f++)
                o = fmaf(g_W2T[f*384 + row], sm[AXB + s*16 + f], o);
            g_olast[(long)bn*H_ + h*16 + d] = o;
        }
        // next phase1 is safe without a sync here (buffers it writes were last
        // read before the phase2-sync; AXB rewrite happens after the next
        // phase2-sync which phase5 threads reach only after finishing).
    }
    if (tid < 192) {
        #pragma unroll
        for (int q = 0; q < 3; q++) {
            int v = tid + q*192;
            int row = v / 12, c4 = v - row*12;
            *(float4*)&tattn[(long)bn*2304 + row*48 + c4*4] =
                make_float4(racc[q*4+0]*0.125f, racc[q*4+1]*0.125f,
                            racc[q*4+2]*0.125f, racc[q*4+3]*0.125f);
        }
    }
    // folded hlast
    if (tid < 128) {
        float hsum = proj_b[tid];
        const float4* pw = (const float4*)(proj_w + tid*16);
        #pragma unroll
        for (int q = 0; q < 4; q++) {
            float4 w4 = pw[q];
            hsum = fmaf(w4.x, sm[AX + 47*XS + q*4 + 0], hsum);
            hsum = fmaf(w4.y, sm[AX + 47*XS + q*4 + 1], hsum);
            hsum = fmaf(w4.z, sm[AX + 47*XS + q*4 + 2], hsum);
            hsum = fmaf(w4.w, sm[AX + 47*XS + q*4 + 3], hsum);
        }
        g_hlast[(long)bn*H_ + tid] = hsum;
    }
    // folded s_repr (b==0 blocks only)
    if (bn < 512 && tid < 128) {
        float v = stat_b[tid];
        #pragma unroll
        for (int f = 0; f < S_; f++)
            v = fmaf(x_static[n*S_ + f], stat_w[tid*S_ + f], v);
        v = fmaxf(v, 0.f);
        #pragma unroll
        for (int bb = 0; bb < B_; bb++)
            g_node3[((long)(bb*N_ + n))*384 + 128 + tid] = v;
    }
}

// ---------------- 16x128 tiled GEMM, float4 B-fragment + float4 stores ----------------
// bt=1: B is (N,K) row-major. epi: 0 none, 1 relu, 2 gelu, 3 LN(+res),
// 4 = write C + s1/s2 dots, 5 = relu + head projections
__global__ __launch_bounds__(256) void gemm16_kernel(
    const float* __restrict__ A, const float* __restrict__ Bm,
    const float* __restrict__ bias, float* __restrict__ C,
    int K, int lda, int ldb, int ldc, int bt, int epi,
    const float* __restrict__ res, const float* __restrict__ gw, const float* __restrict__ bw,
    const float* __restrict__ ga, float* __restrict__ s1o, float* __restrict__ s2o,
    const float* __restrict__ hwreg, const float* __restrict__ hbreg,
    const float* __restrict__ hwrisk, const float* __restrict__ hbrisk,
    const float* __restrict__ hwwarn, const float* __restrict__ hbwarn,
    float* __restrict__ hout,
    long strA, long strB, long strC)
{
    A  += (long)blockIdx.z * strA;
    Bm += (long)blockIdx.z * strB;
    C  += (long)blockIdx.z * strC;
    const int rowbase = blockIdx.x * 16;
    const int colbase = blockIdx.y * 128;
    __shared__ float As[32][17];
    __shared__ float Bs[32][132];
    const int tid = threadIdx.x;
    const int tx = tid & 31, ty = tid >> 5;
    float acc[2][4] = {};
    for (int k0 = 0; k0 < K; k0 += 32) {
        #pragma unroll
        for (int it = 0; it < 2; it++) {
            int idx = tid + it*256;
            int r = idx >> 5, kk = idx & 31;
            As[kk][r] = A[(long)(rowbase + r)*lda + k0 + kk];
        }
        if (bt) {
            #pragma unroll
            for (int it = 0; it < 4; it++) {
                int q = tid + it*256;          // 0..1023
                int c = q & 127, kq = q >> 7;  // kq 0..7
                float4 bv = *(const float4*)&Bm[(long)(colbase + c)*ldb + k0 + kq*4];
                Bs[kq*4+0][c] = bv.x; Bs[kq*4+1][c] = bv.y;
                Bs[kq*4+2][c] = bv.z; Bs[kq*4+3][c] = bv.w;
            }
        } else {
            #pragma unroll
            for (int it = 0; it < 4; it++) {
                int q = tid + it*256;
                int c4 = q & 31, kk = q >> 5;
                float4 bv = *(const float4*)&Bm[(long)(k0 + kk)*ldb + colbase + c4*4];
                *(float4*)&Bs[kk][c4*4] = bv;
            }
        }
        __syncthreads();
        #pragma unroll
        for (int kk = 0; kk < 32; kk++) {
            float a0 = As[kk][ty], a1 = As[kk][ty + 8];
            float4 b4 = *(const float4*)&Bs[kk][tx*4];
            acc[0][0] = fmaf(a0, b4.x, acc[0][0]);
            acc[0][1] = fmaf(a0, b4.y, acc[0][1]);
            acc[0][2] = fmaf(a0, b4.z, acc[0][2]);
            acc[0][3] = fmaf(a0, b4.w, acc[0][3]);
            acc[1][0] = fmaf(a1, b4.x, acc[1][0]);
            acc[1][1] = fmaf(a1, b4.y, acc[1][1]);
            acc[1][2] = fmaf(a1, b4.z, acc[1][2]);
            acc[1][3] = fmaf(a1, b4.w, acc[1][3]);
        }
        __syncthreads();
    }
    if (epi == 3) {
        float4 b4 = *(const float4*)&bias[tx*4];
        float4 g4 = *(const float4*)&gw[tx*4];
        float4 w4 = *(const float4*)&bw[tx*4];
        #pragma unroll
        for (int i = 0; i < 2; i++) {
            int r = rowbase + ty + 8*i;
            float4 r4 = *(const float4*)&res[(long)r*128 + tx*4];
            float v[4];
            v[0] = acc[i][0] + b4.x + r4.x; v[1] = acc[i][1] + b4.y + r4.y;
            v[2] = acc[i][2] + b4.z + r4.z; v[3] = acc[i][3] + b4.w + r4.w;
            float m = warp_red_sum(v[0]+v[1]+v[2]+v[3]) * (1.f/128.f);
            float d2 = 0.f;
            #pragma unroll
            for (int j = 0; j < 4; j++) { float d = v[j]-m; d2 += d*d; }
            float var = warp_red_sum(d2) * (1.f/128.f);
            float inv = rsqrtf(var + 1e-5f);
            float4 o;
            o.x = (v[0]-m)*inv*g4.x + w4.x; o.y = (v[1]-m)*inv*g4.y + w4.y;
            o.z = (v[2]-m)*inv*g4.z + w4.z; o.w = (v[3]-m)*inv*g4.w + w4.w;
            *(float4*)&C[(long)r*ldc + tx*4] = o;
        }
    } else if (epi == 4) {
        float4 a1v = *(const float4*)&ga[tx*4];
        float4 a2v = *(const float4*)&ga[128 + tx*4];
        #pragma unroll
        for (int i = 0; i < 2; i++) {
            int r = rowbase + ty + 8*i;
            float4 o = make_float4(acc[i][0], acc[i][1], acc[i][2], acc[i][3]);
            *(float4*)&C[(long)r*ldc + tx*4] = o;
            float p1 = o.x*a1v.x + o.y*a1v.y + o.z*a1v.z + o.w*a1v.w;
            float p2 = o.x*a2v.x + o.y*a2v.y + o.z*a2v.z + o.w*a2v.w;
            p1 = warp_red_sum(p1);
            p2 = warp_red_sum(p2);
            if (tx == 0) { s1o[r] = p1; s2o[r] = p2; }
        }
    } else if (epi == 5) {
        float4 b4 = *(const float4*)&bias[tx*4];
        #pragma unroll
        for (int i = 0; i < 2; i++) {
            float4 o;
            o.x = fmaxf(acc[i][0] + b4.x, 0.f); o.y = fmaxf(acc[i][1] + b4.y, 0.f);
            o.z = fmaxf(acc[i][2] + b4.z, 0.f); o.w = fmaxf(acc[i][3] + b4.w, 0.f);
            *(float4*)&Bs[ty + 8*i][tx*4] = o;
        }
        __syncthreads();
        for (int p = tid; p < 480; p += 256) {
            int r = p / 30, o = p - 30*r;
            const float* w; float bb; long off;
            if (o < 6)       { w = hwreg  + o*H_;        bb = hbreg[o];        off = OFF_REG  + (long)(rowbase+r)*6  + o; }
            else if (o < 24) { int k = o-6;  w = hwrisk + k*H_; bb = hbrisk[k]; off = OFF_RISK + (long)(rowbase+r)*18 + k; }
            else             { int k = o-24; w = hwwarn + k*H_; bb = hbwarn[k]; off = OFF_WARN + (long)(rowbase+r)*6  + k; }
            float sacc = bb;
            #pragma unroll 8
            for (int c = 0; c < H_; c++)
                sacc = fmaf(Bs[r][c], w[c], sacc);
            hout[off] = sacc;
        }
    } else {
        float4 b4 = bias ? *(const float4*)&bias[colbase + tx*4]
                         : make_float4(0.f,0.f,0.f,0.f);
        #pragma unroll
        for (int i = 0; i < 2; i++) {
            int r = rowbase + ty + 8*i;
            float v[4];
            v[0] = acc[i][0] + b4.x; v[1] = acc[i][1] + b4.y;
            v[2] = acc[i][2] + b4.z; v[3] = acc[i][3] + b4.w;
            if (epi == 1) {
                #pragma unroll
                for (int j = 0; j < 4; j++) v[j] = fmaxf(v[j], 0.f);
            } else if (epi == 2) {
                #pragma unroll
                for (int j = 0; j < 4; j++)
                    v[j] = 0.5f*v[j]*(1.f + erff(v[j]*0.70710678118654752f));
            }
            *(float4*)&C[(long)r*ldc + colbase + tx*4] =
                make_float4(v[0], v[1], v[2], v[3]);
        }
    }
}

// ---------------- GAT alpha ----------------
__global__ __launch_bounds__(256) void alpha_kernel(const int* __restrict__ adj,
                                                    float* __restrict__ out_alpha)
{
    int bi = blockIdx.x;
    int b = bi >> 9, i = bi & 511;
    int tid = threadIdx.x;
    __shared__ float red[8];
    float s1v = g_s1[b*N_ + i];
    float e[2];
    float mloc = -FLT_MAX;
    #pragma unroll
    for (int u = 0; u < 2; u++) {
        int j = tid + u*256;
        float v = s1v + g_s2[b*N_ + j];
        v = (v >= 0.f) ? v : 0.2f*v;
        if (adj[i*N_ + j] == 0) v = -FLT_MAX;
        e[u] = v;
        mloc = fmaxf(mloc, v);
    }
    mloc = warp_red_max(mloc);
    if ((tid & 31) == 0) red[tid >> 5] = mloc;
    __syncthreads();
    float m = red[0];
    #pragma unroll
    for (int w = 1; w < 8; w++) m = fmaxf(m, red[w]);
    __syncthreads();
    float sloc = 0.f;
    #pragma unroll
    for (int u = 0; u < 2; u++) {
        e[u] = (e[u] == -FLT_MAX) ? 0.f : __expf(e[u] - m);
        sloc += e[u];
    }
    sloc = warp_red_sum(sloc);
    if ((tid & 31) == 0) red[tid >> 5] = sloc;
    __syncthreads();
    float ssum = red[0]+red[1]+red[2]+red[3]+red[4]+red[5]+red[6]+red[7];
    float inv = 1.f/ssum;
    #pragma unroll
    for (int u = 0; u < 2; u++)
        out_alpha[((long)(b*N_ + i))*N_ + tid + u*256] = e[u]*inv;
}

// ---------------- launch ----------------
extern "C" void kernel_launch(void* const* d_in, const int* in_sizes, int n_in,
                              void* d_out, int out_size)
{
    const float* x        = (const float*)d_in[0];
    const float* x_static = (const float*)d_in[1];
    const int*   adj      = (const int*)  d_in[2];
    const float* proj_w   = (const float*)d_in[3];
    const float* proj_b   = (const float*)d_in[4];
    const float* in_w     = (const float*)d_in[5];
    const float* in_b     = (const float*)d_in[6];
    const float* out_w    = (const float*)d_in[7];
    const float* out_b    = (const float*)d_in[8];
    const float* ln1_g    = (const float*)d_in[9];
    const float* ln1_b    = (const float*)d_in[10];
    const float* ffn_w1   = (const float*)d_in[11];
    const float* ffn_b1   = (const float*)d_in[12];
    const float* ffn_w2   = (const float*)d_in[13];
    const float* ffn_b2   = (const float*)d_in[14];
    const float* ln2_g    = (const float*)d_in[15];
    const float* ln2_b    = (const float*)d_in[16];
    const float* stat_w   = (const float*)d_in[17];
    const float* stat_b   = (const float*)d_in[18];
    const float* gat_w    = (const float*)d_in[19];
    const float* gat_a    = (const float*)d_in[20];
    const float* fuse_w   = (const float*)d_in[21];
    const float* fuse_b   = (const float*)d_in[22];
    const float* reg_w    = (const float*)d_in[23];
    const float* reg_b    = (const float*)d_in[24];
    const float* risk_w   = (const float*)d_in[25];
    const float* risk_b   = (const float*)d_in[26];
    const float* warn_w   = (const float*)d_in[27];
    const float* warn_b   = (const float*)d_in[28];
    float* out = (float*)d_out;

    float *p_olast, *p_hlast, *p_hln1, *p_ffn1, *p_node3, *p_gh, *p_s1, *p_s2;
    cudaGetSymbolAddress((void**)&p_olast, g_olast);
    cudaGetSymbolAddress((void**)&p_hlast, g_hlast);
    cudaGetSymbolAddress((void**)&p_hln1,  g_hln1);
    cudaGetSymbolAddress((void**)&p_ffn1,  g_ffn1);
    cudaGetSymbolAddress((void**)&p_node3, g_node3);
    cudaGetSymbolAddress((void**)&p_gh,    g_gh);
    cudaGetSymbolAddress((void**)&p_s1,    g_s1);
    cudaGetSymbolAddress((void**)&p_s2,    g_s2);

    const int ATTN4_SMEM = ATTN4_FLOATS * 4;  // 57856 bytes
    cudaFuncSetAttribute(attn4_kernel, cudaFuncAttributeMaxDynamicSharedMemorySize, ATTN4_SMEM);

    // 0-2: prep
    prepw2_kernel<<<384, 32>>>(in_w, in_b, proj_w, proj_b);
    prep2m_kernel<<<8, 256>>>();
    prep2rc_kernel<<<8, 64>>>();
    // 3: attention (+hlast +srepr)
    attn4_kernel<<<BN_, 256, ATTN4_SMEM>>>(x, proj_w, proj_b, x_static, stat_w, stat_b,
                                           out + OFF_TATTN);

    // out-proj + LN1 fused
    gemm16_kernel<<<dim3(BN_/16,1,1),256>>>(p_olast, out_w, out_b, p_hln1,
        128, 128, 128, 128, 1, 3, p_hlast, ln1_g, ln1_b,
        nullptr, nullptr, nullptr, nullptr, nullptr, nullptr, nullptr, nullptr, nullptr, nullptr,
        0, 0, 0);
    // FFN1 (gelu)
    gemm16_kernel<<<dim3(BN_/16,2,1),256>>>(p_hln1, ffn_w1, ffn_b1, p_ffn1,
        128, 128, 128, 256, 1, 2, nullptr, nullptr, nullptr,
        nullptr, nullptr, nullptr, nullptr, nullptr, nullptr, nullptr, nullptr, nullptr, nullptr,
        0, 0, 0);
    // FFN2 + LN2 fused -> node3[:,0:128]
    gemm16_kernel<<<dim3(BN_/16,1,1),256>>>(p_ffn1, ffn_w2, ffn_b2, p_node3,
        256, 256, 256, 384, 1, 3, p_hln1, ln2_g, ln2_b,
        nullptr, nullptr, nullptr, nullptr, nullptr, nullptr, nullptr, nullptr, nullptr, nullptr,
        0, 0, 0);
    // gh = node[:, :256] @ gat_w^T  (+ fused s1/s2)
    gemm16_kernel<<<dim3(BN_/16,1,1),256>>>(p_node3, gat_w, nullptr, p_gh,
        256, 384, 256, 128, 1, 4, nullptr, nullptr, nullptr,
        gat_a, p_s1, p_s2, nullptr, nullptr, nullptr, nullptr, nullptr, nullptr, nullptr,
        0, 0, 0);
    alpha_kernel<<<BN_, 256>>>(adj, out + OFF_ALPHA);
    // g_repr = alpha @ gh -> node3[:,256:384]
    gemm16_kernel<<<dim3(N_/16,1,B_),256>>>(out + OFF_ALPHA, p_gh, nullptr,
        p_node3 + 256, 512, 512, 128, 384, 0, 0, nullptr, nullptr, nullptr,
        nullptr, nullptr, nullptr, nullptr, nullptr, nullptr, nullptr, nullptr, nullptr, nullptr,
        (long)N_*N_, (long)N_*H_, (long)N_*384);
    // fused projection (relu) + heads
    gemm16_kernel<<<dim3(BN_/16,1,1),256>>>(p_node3, fuse_w, fuse_b, nullptr,
        384, 384, 384, 128, 1, 5, nullptr, nullptr, nullptr,
        nullptr, nullptr, nullptr,
        reg_w, reg_b, risk_w, risk_b, warn_w, warn_b, out,
        0, 0, 0);

    (void)in_sizes; (void)n_in; (void)out_size;
}

// round 11
// speedup vs baseline: 1.5756x; 1.0686x over previous
#include <cuda_runtime.h>
#include <math.h>
#include <float.h>

#define B_ 8
#define T_ 48
#define N_ 512
#define F_ 16
#define S_ 12
#define H_ 128
#define NH_ 8
#define HZ_ 6
#define NC_ 3
#define BN_ (B_*N_)   /* 4096 */

#define OFF_REG   0L
#define OFF_RISK  24576L
#define OFF_WARN  98304L
#define OFF_TATTN 122880L
#define OFF_ALPHA 9560064L

// ---------------- scratch ----------------
__device__ __align__(16) float g_W2T[16*384];
__device__ __align__(16) float g_b2[384];
__device__ __align__(16) float g_Mh[8*256];
__device__ __align__(16) float g_rh[8*16];
__device__ __align__(16) float g_ch[8*16];
__device__ __align__(16) float g_cst[8];
__device__ __align__(16) float g_hlast[BN_*H_];
__device__ __align__(16) float g_olast[BN_*H_];
__device__ __align__(16) float g_node3[BN_*3*H_];
__device__ __align__(16) float g_gh[BN_*H_];
__device__ __align__(16) float g_s1[BN_];
__device__ __align__(16) float g_s2[BN_];

// ---------------- helpers ----------------
__device__ __forceinline__ float warp_red_sum(float v) {
    #pragma unroll
    for (int o = 16; o > 0; o >>= 1) v += __shfl_xor_sync(0xffffffffu, v, o);
    return v;
}
__device__ __forceinline__ float warp_red_max(float v) {
    #pragma unroll
    for (int o = 16; o > 0; o >>= 1) v = fmaxf(v, __shfl_xor_sync(0xffffffffu, v, o));
    return v;
}

// ---------------- W2 = in_w @ proj_w ; b2 = in_w @ proj_b + in_b ----------------
__global__ void prepw2_kernel(const float* __restrict__ in_w, const float* __restrict__ in_b,
                              const float* __restrict__ proj_w, const float* __restrict__ proj_b)
{
    int j = blockIdx.x;
    int lane = threadIdx.x;
    float wreg[4];
    #pragma unroll
    for (int u = 0; u < 4; u++) wreg[u] = in_w[j*H_ + lane + 32*u];
    float pb = 0.f;
    #pragma unroll
    for (int u = 0; u < 4; u++) pb += wreg[u] * proj_b[lane + 32*u];
    pb = warp_red_sum(pb);
    if (lane == 0) g_b2[j] = pb + in_b[j];
    for (int f = 0; f < 16; f++) {
        float s = 0.f;
        #pragma unroll
        for (int u = 0; u < 4; u++) s += wreg[u] * proj_w[(lane + 32*u)*16 + f];
        s = warp_red_sum(s);
        if (lane == 0) g_W2T[f*384 + j] = s;
    }
}

// ---------------- per-head score matrices ----------------
__global__ __launch_bounds__(256) void prep2m_kernel()
{
    int h = blockIdx.x;
    int f = threadIdx.x >> 4, g = threadIdx.x & 15;
    float s = 0.f;
    #pragma unroll
    for (int d = 0; d < 16; d++)
        s = fmaf(g_W2T[f*384 + h*16 + d], g_W2T[g*384 + 128 + h*16 + d], s);
    g_Mh[h*256 + f*16 + g] = 0.25f*s;
}
__global__ void prep2rc_kernel()
{
    int h = blockIdx.x, tid = threadIdx.x;
    if (tid < 16) {
        float s = 0.f;
        #pragma unroll
        for (int d = 0; d < 16; d++)
            s = fmaf(g_W2T[tid*384 + h*16 + d], g_b2[128 + h*16 + d], s);
        g_rh[h*16 + tid] = 0.25f*s;
    } else if (tid < 32) {
        int g = tid - 16;
        float s = 0.f;
        #pragma unroll
        for (int d = 0; d < 16; d++)
            s = fmaf(g_b2[h*16 + d], g_W2T[g*384 + 128 + h*16 + d], s);
        g_ch[h*16 + g] = 0.25f*s;
    } else if (tid == 32) {
        float s = 0.f;
        #pragma unroll
        for (int d = 0; d < 16; d++)
            s = fmaf(g_b2[h*16 + d], g_b2[128 + h*16 + d], s);
        g_cst[h] = 0.25f*s;
    }
}

// ---------------- attention v4 (proven @189.9us; offsets restored to R8 values) ----------------
#define XS 20
#define YS 16
#define SSL 52
#define AX   0        /* 48*20 = 960 */
#define AY   960      /* 4*48*16 = 3072 */
#define AS   4032     /* 4*48*52 = 9984 -> ends 14016 */
#define AU   14016    /* 192 */
#define AW   14208    /* 192 */
#define AXB  14400    /* 64 */
#define ATTN4_FLOATS 14464

__global__ __launch_bounds__(256,3) void attn4_kernel(const float* __restrict__ x,
    const float* __restrict__ proj_w, const float* __restrict__ proj_b,
    const float* __restrict__ x_static, const float* __restrict__ stat_w,
    const float* __restrict__ stat_b,
    float* __restrict__ tattn)
{
    extern __shared__ float sm[];
    const int bn = blockIdx.x;
    const int b = bn >> 9, n = bn & 511;
    const int tid = threadIdx.x;

    if (tid < 192) {
        int t = tid >> 2, q = tid & 3;
        float4 v = ((const float4*)(x + (((long)b*T_ + t)*N_ + n)*F_))[q];
        *(float4*)&sm[AX + t*XS + q*4] = v;
    }
    float racc[12];
    #pragma unroll
    for (int k = 0; k < 12; k++) racc[k] = 0.f;
    __syncthreads();

    const int s = tid >> 6, t64 = tid & 63;
    float* sYs = sm + AY + s*768;
    float* sSs = sm + AS + s*2496;

    for (int g = 0; g < 2; g++) {
        const int h = g*4 + s;
        {
            int i0 = (t64 & 15)*3, q4 = t64 >> 4;
            const float4* M4 = (const float4*)(g_Mh + h*256) + q4;
            float acc[3][4] = {};
            #pragma unroll
            for (int f4 = 0; f4 < 4; f4++) {
                float xr[3][4];
                #pragma unroll
                for (int r = 0; r < 3; r++)
                    *(float4*)xr[r] = *(const float4*)&sm[AX + (i0+r)*XS + f4*4];
                #pragma unroll
                for (int u = 0; u < 4; u++) {
                    float4 mv = M4[(f4*4+u)*4];
                    #pragma unroll
                    for (int r = 0; r < 3; r++) {
                        acc[r][0] = fmaf(xr[r][u], mv.x, acc[r][0]);
                        acc[r][1] = fmaf(xr[r][u], mv.y, acc[r][1]);
                        acc[r][2] = fmaf(xr[r][u], mv.z, acc[r][2]);
                        acc[r][3] = fmaf(xr[r][u], mv.w, acc[r][3]);
                    }
                }
            }
            #pragma unroll
            for (int r = 0; r < 3; r++)
                *(float4*)&sYs[(i0+r)*YS + q4*4] =
                    make_float4(acc[r][0], acc[r][1], acc[r][2], acc[r][3]);
            if (t64 < 48) {
                int i = t64;
                float uu = 0.f, ww = g_cst[h];
                const float4* rh4 = (const float4*)(g_rh + h*16);
                const float4* ch4 = (const float4*)(g_ch + h*16);
                #pragma unroll
                for (int q = 0; q < 4; q++) {
                    float xv[4];
                    *(float4*)xv = *(const float4*)&sm[AX + i*XS + q*4];
                    float4 rv = rh4[q], cv = ch4[q];
                    uu = fmaf(rv.x, xv[0], uu); uu = fmaf(rv.y, xv[1], uu);
                    uu = fmaf(rv.z, xv[2], uu); uu = fmaf(rv.w, xv[3], uu);
                    ww = fmaf(cv.x, xv[0], ww); ww = fmaf(cv.y, xv[1], ww);
                    ww = fmaf(cv.z, xv[2], ww); ww = fmaf(cv.w, xv[3], ww);
                }
                sm[AU + s*48 + i] = uu;
                sm[AW + s*48 + i] = ww;
            }
        }
        __syncthreads();
        {
            int ti = t64 >> 3, tj = t64 & 7;
            int i0 = ti*6, j0 = tj*6;
            float acc[6][6] = {};
            #pragma unroll
            for (int k4 = 0; k4 < 4; k4++) {
                float yv[6][4];
                #pragma unroll
                for (int r = 0; r < 6; r++)
                    *(float4*)yv[r] = *(const float4*)&sYs[(i0+r)*YS + k4*4];
                #pragma unroll
                for (int c = 0; c < 6; c++) {
                    float xc[4];
                    *(float4*)xc = *(const float4*)&sm[AX + (j0+c)*XS + k4*4];
                    #pragma unroll
                    for (int r = 0; r < 6; r++) {
                        acc[r][c] = fmaf(yv[r][0], xc[0], acc[r][c]);
                        acc[r][c] = fmaf(yv[r][1], xc[1], acc[r][c]);
                        acc[r][c] = fmaf(yv[r][2], xc[2], acc[r][c]);
                        acc[r][c] = fmaf(yv[r][3], xc[3], acc[r][c]);
                    }
                }
            }
            float wv[6];
            #pragma unroll
            for (int c = 0; c < 6; c++) wv[c] = sm[AW + s*48 + j0 + c];
            #pragma unroll
            for (int r = 0; r < 6; r++) {
                float uu = sm[AU + s*48 + i0 + r];
                #pragma unroll
                for (int c = 0; c < 6; c++) acc[r][c] += uu + wv[c];
            }
            #pragma unroll
            for (int r = 0; r < 6; r++) {
                float m = acc[r][0];
                #pragma unroll
                for (int c = 1; c < 6; c++) m = fmaxf(m, acc[r][c]);
                m = fmaxf(m, __shfl_xor_sync(0xffffffffu, m, 1));
                m = fmaxf(m, __shfl_xor_sync(0xffffffffu, m, 2));
                m = fmaxf(m, __shfl_xor_sync(0xffffffffu, m, 4));
                float rs = 0.f;
                #pragma unroll
                for (int c = 0; c < 6; c++) {
                    float e = __expf(acc[r][c] - m);
                    acc[r][c] = e;
                    rs += e;
                }
                rs += __shfl_xor_sync(0xffffffffu, rs, 1);
                rs += __shfl_xor_sync(0xffffffffu, rs, 2);
                rs += __shfl_xor_sync(0xffffffffu, rs, 4);
                float inv = 1.f/rs;
                #pragma unroll
                for (int c = 0; c < 6; c++)
                    sSs[(i0+r)*SSL + j0 + c] = acc[r][c]*inv;
            }
        }
        __syncthreads();
        if (tid < 192) {
            #pragma unroll
            for (int q = 0; q < 3; q++) {
                int v = tid + q*192;
                int row = v / 12, c4 = v - row*12;
                int off = AS + row*SSL + c4*4;
                float4 a0 = *(const float4*)&sm[off];
                float4 a1 = *(const float4*)&sm[off + 2496];
                float4 a2 = *(const float4*)&sm[off + 2*2496];
                float4 a3 = *(const float4*)&sm[off + 3*2496];
                racc[q*4+0] += a0.x + a1.x + a2.x + a3.x;
                racc[q*4+1] += a0.y + a1.y + a2.y + a3.y;
                racc[q*4+2] += a0.z + a1.z + a2.z + a3.z;
                racc[q*4+3] += a0.w + a1.w + a2.w + a3.w;
            }
        }
        if (t64 < 16) {
            int f = t64;
            float xb = 0.f;
            #pragma unroll
            for (int k = 0; k < 48; k++)
                xb = fmaf(sSs[47*SSL + k], sm[AX + k*XS + f], xb);
            sm[AXB + s*16 + f] = xb;
        }
        __syncthreads();
        if (t64 < 16) {
            int d = t64;
            int row = 256 + h*16 + d;
            float o = g_b2[row];
            #pragma unroll
            for (int f = 0; f < 16; f++)
                o = fmaf(g_W2T[f*384 + row], sm[AXB + s*16 + f], o);
            g_olast[(long)bn*H_ + h*16 + d] = o;
        }
    }
    if (tid < 192) {
        #pragma unroll
        for (int q = 0; q < 3; q++) {
            int v = tid + q*192;
            int row = v / 12, c4 = v - row*12;
            *(float4*)&tattn[(long)bn*2304 + row*48 + c4*4] =
                make_float4(racc[q*4+0]*0.125f, racc[q*4+1]*0.125f,
                            racc[q*4+2]*0.125f, racc[q*4+3]*0.125f);
        }
    }
    if (tid < 128) {
        float hsum = proj_b[tid];
        const float4* pw = (const float4*)(proj_w + tid*16);
        #pragma unroll
        for (int q = 0; q < 4; q++) {
            float4 w4 = pw[q];
            hsum = fmaf(w4.x, sm[AX + 47*XS + q*4 + 0], hsum);
            hsum = fmaf(w4.y, sm[AX + 47*XS + q*4 + 1], hsum);
            hsum = fmaf(w4.z, sm[AX + 47*XS + q*4 + 2], hsum);
            hsum = fmaf(w4.w, sm[AX + 47*XS + q*4 + 3], hsum);
        }
        g_hlast[(long)bn*H_ + tid] = hsum;
    }
    if (bn < 512 && tid < 128) {
        float v = stat_b[tid];
        #pragma unroll
        for (int f = 0; f < S_; f++)
            v = fmaf(x_static[n*S_ + f], stat_w[tid*S_ + f], v);
        v = fmaxf(v, 0.f);
        #pragma unroll
        for (int bb = 0; bb < B_; bb++)
            g_node3[((long)(bb*N_ + n))*384 + 128 + tid] = v;
    }
}

// ---------------- tail1: outproj+LN1 -> FFN1+gelu -> FFN2+LN2 -> gh+s1/s2 ----------------
__global__ __launch_bounds__(256) void tail1_kernel(
    const float* __restrict__ out_w, const float* __restrict__ out_b,
    const float* __restrict__ ln1_g, const float* __restrict__ ln1_b,
    const float* __restrict__ ffn_w1, const float* __restrict__ ffn_b1,
    const float* __restrict__ ffn_w2, const float* __restrict__ ffn_b2,
    const float* __restrict__ ln2_g, const float* __restrict__ ln2_b,
    const float* __restrict__ gat_w, const float* __restrict__ gat_a)
{
    const int rowbase = blockIdx.x * 16;
    __shared__ float res1[16][132];
    __shared__ float actB[16][260];
    __shared__ float Bs[32][132];
    const int tid = threadIdx.x;
    const int tx = tid & 31, ty = tid >> 5;

    for (int idx = tid; idx < 16*32; idx += 256) {
        int r = idx >> 5, c4 = idx & 31;
        *(float4*)&actB[r][c4*4] = *(const float4*)&g_olast[(long)(rowbase+r)*128 + c4*4];
    }

    // ---- stage A: out-proj (K=128) + bias + residual + LN1 -> res1 ----
    {
        float acc[2][4] = {};
        for (int k0 = 0; k0 < 128; k0 += 32) {
            #pragma unroll
            for (int it = 0; it < 4; it++) {
                int q = tid + it*256;
                int c = q & 127, kq = q >> 7;
                float4 bv = *(const float4*)&out_w[(long)c*128 + k0 + kq*4];
                Bs[kq*4+0][c] = bv.x; Bs[kq*4+1][c] = bv.y;
                Bs[kq*4+2][c] = bv.z; Bs[kq*4+3][c] = bv.w;
            }
            __syncthreads();
            #pragma unroll
            for (int kk = 0; kk < 32; kk++) {
                float a0 = actB[ty][k0+kk], a1 = actB[ty+8][k0+kk];
                float4 b4 = *(const float4*)&Bs[kk][tx*4];
                acc[0][0] = fmaf(a0, b4.x, acc[0][0]); acc[0][1] = fmaf(a0, b4.y, acc[0][1]);
                acc[0][2] = fmaf(a0, b4.z, acc[0][2]); acc[0][3] = fmaf(a0, b4.w, acc[0][3]);
                acc[1][0] = fmaf(a1, b4.x, acc[1][0]); acc[1][1] = fmaf(a1, b4.y, acc[1][1]);
                acc[1][2] = fmaf(a1, b4.z, acc[1][2]); acc[1][3] = fmaf(a1, b4.w, acc[1][3]);
            }
            __syncthreads();
        }
        float4 ob = *(const float4*)&out_b[tx*4];
        float4 g4 = *(const float4*)&ln1_g[tx*4];
        float4 w4 = *(const float4*)&ln1_b[tx*4];
        #pragma unroll
        for (int i = 0; i < 2; i++) {
            int lr = ty + 8*i;
            float4 r4 = *(const float4*)&g_hlast[(long)(rowbase+lr)*128 + tx*4];
            float v[4];
            v[0] = acc[i][0] + ob.x + r4.x; v[1] = acc[i][1] + ob.y + r4.y;
            v[2] = acc[i][2] + ob.z + r4.z; v[3] = acc[i][3] + ob.w + r4.w;
            float m = warp_red_sum(v[0]+v[1]+v[2]+v[3]) * (1.f/128.f);
            float d2 = 0.f;
            #pragma unroll
            for (int j = 0; j < 4; j++) { float d = v[j]-m; d2 += d*d; }
            float var = warp_red_sum(d2) * (1.f/128.f);
            float inv = rsqrtf(var + 1e-5f);
            float4 o;
            o.x = (v[0]-m)*inv*g4.x + w4.x; o.y = (v[1]-m)*inv*g4.y + w4.y;
            o.z = (v[2]-m)*inv*g4.z + w4.z; o.w = (v[3]-m)*inv*g4.w + w4.w;
            *(float4*)&res1[lr][tx*4] = o;
        }
    }
    __syncthreads();

    // ---- stage B: FFN1 (K=128, 2 col-blocks) + gelu -> actB[:, 0:256] ----
    for (int cb = 0; cb < 2; cb++) {
        float acc[2][4] = {};
        for (int k0 = 0; k0 < 128; k0 += 32) {
            #pragma unroll
            for (int it = 0; it < 4; it++) {
                int q = tid + it*256;
                int c = q & 127, kq = q >> 7;
                float4 bv = *(const float4*)&ffn_w1[(long)(cb*128 + c)*128 + k0 + kq*4];
                Bs[kq*4+0][c] = bv.x; Bs[kq*4+1][c] = bv.y;
                Bs[kq*4+2][c] = bv.z; Bs[kq*4+3][c] = bv.w;
            }
            __syncthreads();
            #pragma unroll
            for (int kk = 0; kk < 32; kk++) {
                float a0 = res1[ty][k0+kk], a1 = res1[ty+8][k0+kk];
                float4 b4 = *(const float4*)&Bs[kk][tx*4];
                acc[0][0] = fmaf(a0, b4.x, acc[0][0]); acc[0][1] = fmaf(a0, b4.y, acc[0][1]);
                acc[0][2] = fmaf(a0, b4.z, acc[0][2]); acc[0][3] = fmaf(a0, b4.w, acc[0][3]);
                acc[1][0] = fmaf(a1, b4.x, acc[1][0]); acc[1][1] = fmaf(a1, b4.y, acc[1][1]);
                acc[1][2] = fmaf(a1, b4.z, acc[1][2]); acc[1][3] = fmaf(a1, b4.w, acc[1][3]);
            }
            __syncthreads();
        }
        float4 fb = *(const float4*)&ffn_b1[cb*128 + tx*4];
        #pragma unroll
        for (int i = 0; i < 2; i++) {
            float v[4];
            v[0] = acc[i][0] + fb.x; v[1] = acc[i][1] + fb.y;
            v[2] = acc[i][2] + fb.z; v[3] = acc[i][3] + fb.w;
            #pragma unroll
            for (int j = 0; j < 4; j++)
                v[j] = 0.5f*v[j]*(1.f + erff(v[j]*0.70710678118654752f));
            *(float4*)&actB[ty + 8*i][cb*128 + tx*4] = make_float4(v[0], v[1], v[2], v[3]);
        }
        __syncthreads();
    }

    // ---- stage C: FFN2 (K=256) + bias + residual(res1) + LN2 ----
    {
        float acc[2][4] = {};
        for (int k0 = 0; k0 < 256; k0 += 32) {
            #pragma unroll
            for (int it = 0; it < 4; it++) {
                int q = tid + it*256;
                int c = q & 127, kq = q >> 7;
                float4 bv = *(const float4*)&ffn_w2[(long)c*256 + k0 + kq*4];
                Bs[kq*4+0][c] = bv.x; Bs[kq*4+1][c] = bv.y;
                Bs[kq*4+2][c] = bv.z; Bs[kq*4+3][c] = bv.w;
            }
            __syncthreads();
            #pragma unroll
            for (int kk = 0; kk < 32; kk++) {
                float a0 = actB[ty][k0+kk], a1 = actB[ty+8][k0+kk];
                float4 b4 = *(const float4*)&Bs[kk][tx*4];
                acc[0][0] = fmaf(a0, b4.x, acc[0][0]); acc[0][1] = fmaf(a0, b4.y, acc[0][1]);
                acc[0][2] = fmaf(a0, b4.z, acc[0][2]); acc[0][3] = fmaf(a0, b4.w, acc[0][3]);
                acc[1][0] = fmaf(a1, b4.x, acc[1][0]); acc[1][1] = fmaf(a1, b4.y, acc[1][1]);
                acc[1][2] = fmaf(a1, b4.z, acc[1][2]); acc[1][3] = fmaf(a1, b4.w, acc[1][3]);
            }
            __syncthreads();
        }
        float4 fb = *(const float4*)&ffn_b2[tx*4];
        float4 g4 = *(const float4*)&ln2_g[tx*4];
        float4 w4 = *(const float4*)&ln2_b[tx*4];
        #pragma unroll
        for (int i = 0; i < 2; i++) {
            int lr = ty + 8*i;
            float4 r4 = *(const float4*)&res1[lr][tx*4];
            float v[4];
            v[0] = acc[i][0] + fb.x + r4.x; v[1] = acc[i][1] + fb.y + r4.y;
            v[2] = acc[i][2] + fb.z + r4.z; v[3] = acc[i][3] + fb.w + r4.w;
            float m = warp_red_sum(v[0]+v[1]+v[2]+v[3]) * (1.f/128.f);
            float d2 = 0.f;
            #pragma unroll
            for (int j = 0; j < 4; j++) { float d = v[j]-m; d2 += d*d; }
            float var = warp_red_sum(d2) * (1.f/128.f);
            float inv = rsqrtf(var + 1e-5f);
            float4 o;
            o.x = (v[0]-m)*inv*g4.x + w4.x; o.y = (v[1]-m)*inv*g4.y + w4.y;
            o.z = (v[2]-m)*inv*g4.z + w4.z; o.w = (v[3]-m)*inv*g4.w + w4.w;
            *(float4*)&g_node3[(long)(rowbase+lr)*384 + tx*4] = o;
            *(float4*)&actB[lr][tx*4] = o;
        }
    }
    __syncthreads();
    for (int idx = tid; idx < 16*32; idx += 256) {
        int r = idx >> 5, c4 = idx & 31;
        *(float4*)&actB[r][128 + c4*4] =
            *(const float4*)&g_node3[(long)(rowbase+r)*384 + 128 + c4*4];
    }

    // ---- stage D: gh = node[:,0:256] @ gat_w^T (K=256) + s1/s2 ----
    {
        float acc[2][4] = {};
        for (int k0 = 0; k0 < 256; k0 += 32) {
            #pragma unroll
            for (int it = 0; it < 4; it++) {
                int q = tid + it*256;
                int c = q & 127, kq = q >> 7;
                float4 bv = *(const float4*)&gat_w[(long)c*256 + k0 + kq*4];
                Bs[kq*4+0][c] = bv.x; Bs[kq*4+1][c] = bv.y;
                Bs[kq*4+2][c] = bv.z; Bs[kq*4+3][c] = bv.w;
            }
            __syncthreads();
            #pragma unroll
            for (int kk = 0; kk < 32; kk++) {
                float a0 = actB[ty][k0+kk], a1 = actB[ty+8][k0+kk];
                float4 b4 = *(const float4*)&Bs[kk][tx*4];
                acc[0][0] = fmaf(a0, b4.x, acc[0][0]); acc[0][1] = fmaf(a0, b4.y, acc[0][1]);
                acc[0][2] = fmaf(a0, b4.z, acc[0][2]); acc[0][3] = fmaf(a0, b4.w, acc[0][3]);
                acc[1][0] = fmaf(a1, b4.x, acc[1][0]); acc[1][1] = fmaf(a1, b4.y, acc[1][1]);
                acc[1][2] = fmaf(a1, b4.z, acc[1][2]); acc[1][3] = fmaf(a1, b4.w, acc[1][3]);
            }
            __syncthreads();
        }
        float4 a1v = *(const float4*)&gat_a[tx*4];
        float4 a2v = *(const float4*)&gat_a[128 + tx*4];
        #pragma unroll
        for (int i = 0; i < 2; i++) {
            int r = rowbase + ty + 8*i;
            float4 o = make_float4(acc[i][0], acc[i][1], acc[i][2], acc[i][3]);
            *(float4*)&g_gh[(long)r*128 + tx*4] = o;
            float p1 = o.x*a1v.x + o.y*a1v.y + o.z*a1v.z + o.w*a1v.w;
            float p2 = o.x*a2v.x + o.y*a2v.y + o.z*a2v.z + o.w*a2v.w;
            p1 = warp_red_sum(p1);
            p2 = warp_red_sum(p2);
            if (tx == 0) { g_s1[r] = p1; g_s2[r] = p2; }
        }
    }
}

// ---------------- tail2: GAT alpha (softmax over 512) + alpha@gh -> g_repr ----------------
// static smem: 16*512*4 + 32*128*4 = 49152 B (exactly at the 48KB static cap)
__global__ __launch_bounds__(256) void tail2_kernel(const int* __restrict__ adj,
                                                    float* __restrict__ out_alpha)
{
    const int rowbase = blockIdx.x * 16;   // 16 rows, all same batch b
    const int b = rowbase >> 9;
    __shared__ float alpha_sm[16][512];
    __shared__ float Bs[32][128];
    const int tid = threadIdx.x;
    const int tx = tid & 31, ty = tid >> 5;

    #pragma unroll
    for (int rr = 0; rr < 2; rr++) {
        int lr = ty*2 + rr;
        int i = (rowbase + lr) & 511;
        float s1v = g_s1[rowbase + lr];
        float e[16];
        float mloc = -FLT_MAX;
        #pragma unroll
        for (int u = 0; u < 16; u++) {
            int j = tx + 32*u;
            float v = s1v + g_s2[b*N_ + j];
            v = (v >= 0.f) ? v : 0.2f*v;
            if (adj[i*N_ + j] == 0) v = -FLT_MAX;
            e[u] = v;
            mloc = fmaxf(mloc, v);
        }
        float m = warp_red_max(mloc);
        float sloc = 0.f;
        #pragma unroll
        for (int u = 0; u < 16; u++) {
            e[u] = (e[u] == -FLT_MAX) ? 0.f : __expf(e[u] - m);
            sloc += e[u];
        }
        float inv = 1.f / warp_red_sum(sloc);
        #pragma unroll
        for (int u = 0; u < 16; u++) {
            float a = e[u]*inv;
            alpha_sm[lr][tx + 32*u] = a;
            out_alpha[(long)(rowbase + lr)*N_ + tx + 32*u] = a;
        }
    }
    __syncthreads();

    const float* ghb = g_gh + (long)b*N_*H_;
    float acc[2][4] = {};
    for (int k0 = 0; k0 < 512; k0 += 32) {
        #pragma unroll
        for (int it = 0; it < 4; it++) {
            int q = tid + it*256;
            int c4 = q & 31, kk = q >> 5;
            *(float4*)&Bs[kk][c4*4] = *(const float4*)&ghb[(long)(k0+kk)*128 + c4*4];
        }
        __syncthreads();
        #pragma unroll
        for (int kk = 0; kk < 32; kk++) {
            float a0 = alpha_sm[ty][k0+kk], a1 = alpha_sm[ty+8][k0+kk];
            float4 b4 = *(const float4*)&Bs[kk][tx*4];
            acc[0][0] = fmaf(a0, b4.x, acc[0][0]); acc[0][1] = fmaf(a0, b4.y, acc[0][1]);
            acc[0][2] = fmaf(a0, b4.z, acc[0][2]); acc[0][3] = fmaf(a0, b4.w, acc[0][3]);
            acc[1][0] = fmaf(a1, b4.x, acc[1][0]); acc[1][1] = fmaf(a1, b4.y, acc[1][1]);
            acc[1][2] = fmaf(a1, b4.z, acc[1][2]); acc[1][3] = fmaf(a1, b4.w, acc[1][3]);
        }
        __syncthreads();
    }
    #pragma unroll
    for (int i = 0; i < 2; i++) {
        int r = rowbase + ty + 8*i;
        *(float4*)&g_node3[(long)r*384 + 256 + tx*4] =
            make_float4(acc[i][0], acc[i][1], acc[i][2], acc[i][3]);
    }
}

// ---------------- fuse (relu) + output heads ----------------
__global__ __launch_bounds__(256) void fuse_kernel(
    const float* __restrict__ fuse_w, const float* __restrict__ fuse_b,
    const float* __restrict__ hwreg, const float* __restrict__ hbreg,
    const float* __restrict__ hwrisk, const float* __restrict__ hbrisk,
    const float* __restrict__ hwwarn, const float* __restrict__ hbwarn,
    float* __restrict__ hout)
{
    const int rowbase = blockIdx.x * 16;
    __shared__ float As[32][17];
    __shared__ float Bs[32][132];
    const int tid = threadIdx.x;
    const int tx = tid & 31, ty = tid >> 5;
    float acc[2][4] = {};
    for (int k0 = 0; k0 < 384; k0 += 32) {
        #pragma unroll
        for (int it = 0; it < 2; it++) {
            int idx = tid + it*256;
            int r = idx >> 5, kk = idx & 31;
            As[kk][r] = g_node3[(long)(rowbase + r)*384 + k0 + kk];
        }
        #pragma unroll
        for (int it = 0; it < 4; it++) {
            int q = tid + it*256;
            int c = q & 127, kq = q >> 7;
            float4 bv = *(const float4*)&fuse_w[(long)c*384 + k0 + kq*4];
            Bs[kq*4+0][c] = bv.x; Bs[kq*4+1][c] = bv.y;
            Bs[kq*4+2][c] = bv.z; Bs[kq*4+3][c] = bv.w;
        }
        __syncthreads();
        #pragma unroll
        for (int kk = 0; kk < 32; kk++) {
            float a0 = As[kk][ty], a1 = As[kk][ty + 8];
            float4 b4 = *(const float4*)&Bs[kk][tx*4];
            acc[0][0] = fmaf(a0, b4.x, acc[0][0]); acc[0][1] = fmaf(a0, b4.y, acc[0][1]);
            acc[0][2] = fmaf(a0, b4.z, acc[0][2]); acc[0][3] = fmaf(a0, b4.w, acc[0][3]);
            acc[1][0] = fmaf(a1, b4.x, acc[1][0]); acc[1][1] = fmaf(a1, b4.y, acc[1][1]);
            acc[1][2] = fmaf(a1, b4.z, acc[1][2]); acc[1][3] = fmaf(a1, b4.w, acc[1][3]);
        }
        __syncthreads();
    }
    float4 b4 = *(const float4*)&fuse_b[tx*4];
    #pragma unroll
    for (int i = 0; i < 2; i++) {
        float4 o;
        o.x = fmaxf(acc[i][0] + b4.x, 0.f); o.y = fmaxf(acc[i][1] + b4.y, 0.f);
        o.z = fmaxf(acc[i][2] + b4.z, 0.f); o.w = fmaxf(acc[i][3] + b4.w, 0.f);
        *(float4*)&Bs[ty + 8*i][tx*4] = o;
    }
    __syncthreads();
    for (int p = tid; p < 480; p += 256) {
        int r = p / 30, o = p - 30*r;
        const float* w; float bb; long off;
        if (o < 6)       { w = hwreg  + o*H_;        bb = hbreg[o];        off = OFF_REG  + (long)(rowbase+r)*6  + o; }
        else if (o < 24) { int k = o-6;  w = hwrisk + k*H_; bb = hbrisk[k]; off = OFF_RISK + (long)(rowbase+r)*18 + k; }
        else             { int k = o-24; w = hwwarn + k*H_; bb = hbwarn[k]; off = OFF_WARN + (long)(rowbase+r)*6  + k; }
        float sacc = bb;
        #pragma unroll 8
        for (int c = 0; c < H_; c++)
            sacc = fmaf(Bs[r][c], w[c], sacc);
        hout[off] = sacc;
    }
}

// ---------------- launch ----------------
extern "C" void kernel_launch(void* const* d_in, const int* in_sizes, int n_in,
                              void* d_out, int out_size)
{
    const float* x        = (const float*)d_in[0];
    const float* x_static = (const float*)d_in[1];
    const int*   adj      = (const int*)  d_in[2];
    const float* proj_w   = (const float*)d_in[3];
    const float* proj_b   = (const float*)d_in[4];
    const float* in_w     = (const float*)d_in[5];
    const float* in_b     = (const float*)d_in[6];
    const float* out_w    = (const float*)d_in[7];
    const float* out_b    = (const float*)d_in[8];
    const float* ln1_g    = (const float*)d_in[9];
    const float* ln1_b    = (const float*)d_in[10];
    const float* ffn_w1   = (const float*)d_in[11];
    const float* ffn_b1   = (const float*)d_in[12];
    const float* ffn_w2   = (const float*)d_in[13];
    const float* ffn_b2   = (const float*)d_in[14];
    const float* ln2_g    = (const float*)d_in[15];
    const float* ln2_b    = (const float*)d_in[16];
    const float* stat_w   = (const float*)d_in[17];
    const float* stat_b   = (const float*)d_in[18];
    const float* gat_w    = (const float*)d_in[19];
    const float* gat_a    = (const float*)d_in[20];
    const float* fuse_w   = (const float*)d_in[21];
    const float* fuse_b   = (const float*)d_in[22];
    const float* reg_w    = (const float*)d_in[23];
    const float* reg_b    = (const float*)d_in[24];
    const float* risk_w   = (const float*)d_in[25];
    const float* risk_b   = (const float*)d_in[26];
    const float* warn_w   = (const float*)d_in[27];
    const float* warn_b   = (const float*)d_in[28];
    float* out = (float*)d_out;

    const int ATTN4_SMEM = ATTN4_FLOATS * 4;  // 57856 bytes
    cudaFuncSetAttribute(attn4_kernel, cudaFuncAttributeMaxDynamicSharedMemorySize, ATTN4_SMEM);

    // 0-2: prep
    prepw2_kernel<<<384, 32>>>(in_w, in_b, proj_w, proj_b);
    prep2m_kernel<<<8, 256>>>();
    prep2rc_kernel<<<8, 64>>>();
    // 3: attention (+hlast +srepr)
    attn4_kernel<<<BN_, 256, ATTN4_SMEM>>>(x, proj_w, proj_b, x_static, stat_w, stat_b,
                                           out + OFF_TATTN);
    // 4: transformer tail + GAT projection
    tail1_kernel<<<BN_/16, 256>>>(out_w, out_b, ln1_g, ln1_b,
                                  ffn_w1, ffn_b1, ffn_w2, ffn_b2, ln2_g, ln2_b,
                                  gat_w, gat_a);
    // 5: alpha + g_repr
    tail2_kernel<<<BN_/16, 256>>>(adj, out + OFF_ALPHA);
    // 6: fuse + heads
    fuse_kernel<<<BN_/16, 256>>>(fuse_w, fuse_b,
                                 reg_w, reg_b, risk_w, risk_b, warn_w, warn_b, out);

    (void)in_sizes; (void)n_in; (void)out_size;
}